// round 1
// baseline (speedup 1.0000x reference)
#include <cuda_runtime.h>

#define HW   3136
#define WDIM 56
#define CIN  240
#define MID  120
#define COUT 480
#define NB   32

// Scratch (no cudaMalloc allowed)
__device__ float g_y1 [NB * MID * HW];      // conv1+bn1+relu output
__device__ float g_t  [NB * MID * HW];      // dw+bn2, channel-shuffled
__device__ float g_w3f [COUT * 40];         // w3  * scale3
__device__ float g_wscf[COUT * CIN];        // wsc * scale_sc

// ---------------------------------------------------------------------------
// K0: fold BN scales into weights
// ---------------------------------------------------------------------------
__global__ void k_fold(const float* __restrict__ w3, const float* __restrict__ s3,
                       const float* __restrict__ wsc, const float* __restrict__ ssc) {
    int i = blockIdx.x * 256 + threadIdx.x;
    if (i < COUT * 40) {
        g_w3f[i] = w3[i] * s3[i / 40];
    } else {
        int j = i - COUT * 40;
        if (j < COUT * CIN) g_wscf[j] = wsc[j] * ssc[j / CIN];
    }
}

// ---------------------------------------------------------------------------
// K1: grouped 1x1 conv (G=3) + BN + ReLU -> g_y1
// Per CTA: one image n, one group g, 256 spatial positions, 40 out channels.
// 320 threads: tc = tid%64 (4 spatial each), tr = tid/64 in [0,5) (8 ch each)
// ---------------------------------------------------------------------------
__global__ __launch_bounds__(320, 2)
void k_conv1(const float* __restrict__ x, const float* __restrict__ w1,
             const float* __restrict__ s1, const float* __restrict__ b1) {
    __shared__ __align__(16) float Xs[16 * 256];
    __shared__ __align__(16) float Ws[16 * 44];   // padded row stride 44

    int p0 = blockIdx.x * 256;
    int g  = blockIdx.y;
    int n  = blockIdx.z;
    int tid = threadIdx.x;
    int tc = tid & 63;        // spatial quad
    int tr = tid >> 6;        // 0..4 -> 8 channels each

    float acc[4][8];
#pragma unroll
    for (int i = 0; i < 4; i++)
#pragma unroll
        for (int j = 0; j < 8; j++) acc[i][j] = 0.f;

    const float* xb = x + ((size_t)n * CIN + (size_t)g * 80) * HW;

    for (int cb = 0; cb < 80; cb += 16) {
        __syncthreads();
        // load Xs: 16 rows x 256 cols = 1024 float4
#pragma unroll
        for (int it = 0; it < 4; it++) {
            int f = tid + it * 320;
            if (f < 1024) {
                int r  = f >> 6;
                int c4 = (f & 63) << 2;
                float4 v = make_float4(0.f, 0.f, 0.f, 0.f);
                if (p0 + c4 < HW)
                    v = *(const float4*)(xb + (size_t)(cb + r) * HW + p0 + c4);
                *(float4*)(Xs + r * 256 + c4) = v;
            }
        }
        // load Ws: 16 x 40 = 640
#pragma unroll
        for (int it = 0; it < 2; it++) {
            int e = tid + it * 320;
            int k = e & 15, m = e >> 4;
            Ws[k * 44 + m] = w1[(size_t)(g * 40 + m) * 80 + cb + k];
        }
        __syncthreads();
#pragma unroll
        for (int k = 0; k < 16; k++) {
            float a[4], b[8];
            *(float4*)&a[0] = *(const float4*)(Xs + k * 256 + tc * 4);
            *(float4*)&b[0] = *(const float4*)(Ws + k * 44 + tr * 8);
            *(float4*)&b[4] = *(const float4*)(Ws + k * 44 + tr * 8 + 4);
#pragma unroll
            for (int i = 0; i < 4; i++)
#pragma unroll
                for (int j = 0; j < 8; j++)
                    acc[i][j] = fmaf(a[i], b[j], acc[i][j]);
        }
    }

    if (p0 + tc * 4 < HW) {
#pragma unroll
        for (int j = 0; j < 8; j++) {
            int m = g * 40 + tr * 8 + j;
            float sc = s1[m], sh = b1[m];
            float4 v;
            v.x = fmaxf(fmaf(acc[0][j], sc, sh), 0.f);
            v.y = fmaxf(fmaf(acc[1][j], sc, sh), 0.f);
            v.z = fmaxf(fmaf(acc[2][j], sc, sh), 0.f);
            v.w = fmaxf(fmaf(acc[3][j], sc, sh), 0.f);
            *(float4*)(g_y1 + ((size_t)n * MID + m) * HW + p0 + tc * 4) = v;
        }
    }
}

// ---------------------------------------------------------------------------
// K2: depthwise 3x3 (pad 1) + BN2 + channel shuffle -> g_t
// block (56,4): one image, one channel m, 4 output rows
// shuffle: out channel cs = (m%40)*3 + m/40
// ---------------------------------------------------------------------------
__global__ void k_dw(const float* __restrict__ w2, const float* __restrict__ s2,
                     const float* __restrict__ b2) {
    __shared__ float tile[6][58];
    int h0 = blockIdx.x * 4;
    int m  = blockIdx.y;
    int n  = blockIdx.z;
    int tx = threadIdx.x, ty = threadIdx.y;
    int tid = ty * 56 + tx;

    const float* src = g_y1 + ((size_t)n * MID + m) * HW;
    for (int e = tid; e < 6 * 58; e += 224) {
        int r = e / 58, c = e - r * 58;
        int hh = h0 - 1 + r, ww = c - 1;
        tile[r][c] = (hh >= 0 && hh < 56 && ww >= 0 && ww < 56)
                         ? src[hh * WDIM + ww] : 0.f;
    }
    __syncthreads();

    float wv[9];
#pragma unroll
    for (int q = 0; q < 9; q++) wv[q] = __ldg(&w2[m * 9 + q]);

    float sum = 0.f;
#pragma unroll
    for (int dy = 0; dy < 3; dy++)
#pragma unroll
        for (int dx = 0; dx < 3; dx++)
            sum = fmaf(wv[dy * 3 + dx], tile[ty + dy][tx + dx], sum);

    int cs = (m % 40) * 3 + m / 40;
    g_t[((size_t)n * MID + cs) * HW + (size_t)(h0 + ty) * WDIM + tx]
        = fmaf(s2[m], sum, b2[m]);
}

// ---------------------------------------------------------------------------
// K3 helper: one BK=20 GEMM chunk (load + 20 k-steps, 8x8 thread tile)
// ---------------------------------------------------------------------------
__device__ __forceinline__ void k3_chunk(const float* __restrict__ xsrc,
                                         const float* __restrict__ wsrc,
                                         int wstride, int p0, int tid,
                                         int tc, int tr,
                                         float* Xs, float* Ws,
                                         float acc[8][8]) {
    __syncthreads();
    // Xs: 20 x 128 = 640 float4 (2 per thread)
#pragma unroll
    for (int it = 0; it < 2; it++) {
        int f  = tid + it * 320;
        int r  = f >> 5;
        int c4 = (f & 31) << 2;
        float4 v = make_float4(0.f, 0.f, 0.f, 0.f);
        if (p0 + c4 < HW)
            v = *(const float4*)(xsrc + (size_t)r * HW + p0 + c4);
        *(float4*)(Xs + r * 128 + c4) = v;
    }
    // Ws: 20 x 160 = 3200 scalars (10 per thread), k fast -> coalesced runs of 20
#pragma unroll
    for (int it = 0; it < 10; it++) {
        int e = tid + it * 320;
        int k = e % 20, j = e / 20;
        Ws[k * 164 + j] = wsrc[(size_t)j * wstride + k];
    }
    __syncthreads();
#pragma unroll
    for (int k = 0; k < 20; k++) {
        float a[8], b[8];
        *(float4*)&a[0] = *(const float4*)(Xs + k * 128 + tc * 8);
        *(float4*)&a[4] = *(const float4*)(Xs + k * 128 + tc * 8 + 4);
        *(float4*)&b[0] = *(const float4*)(Ws + k * 164 + tr * 8);
        *(float4*)&b[4] = *(const float4*)(Ws + k * 164 + tr * 8 + 4);
#pragma unroll
        for (int i = 0; i < 8; i++)
#pragma unroll
            for (int j = 0; j < 8; j++)
                acc[i][j] = fmaf(a[i], b[j], acc[i][j]);
    }
}

// ---------------------------------------------------------------------------
// K3: fused conv3(grouped) + relu(bn3) + shortcut 1x1 + bn_sc + add -> out
// Per CTA: image n, group gi (160 out channels), 128 spatial positions.
// 320 threads: tc = tid%16 (8 spatial), tr = tid/16 in [0,20) (8 channels)
// ---------------------------------------------------------------------------
__global__ __launch_bounds__(320, 2)
void k_main(const float* __restrict__ x,
            const float* __restrict__ sh3, const float* __restrict__ shsc,
            float* __restrict__ out) {
    __shared__ __align__(16) float Xs[20 * 128];
    __shared__ __align__(16) float Ws[20 * 164];

    int p0 = blockIdx.x * 128;
    int gi = blockIdx.y;
    int n  = blockIdx.z;
    int tid = threadIdx.x;
    int tc = tid & 15;
    int tr = tid >> 4;        // 0..19
    int co0 = gi * 160;

    float acc[8][8];
#pragma unroll
    for (int i = 0; i < 8; i++)
#pragma unroll
        for (int j = 0; j < 8; j++) acc[i][j] = 0.f;

    // ---- Phase A: conv3 (K = 40 over shuffled g_t, scale3 folded) ----
    const float* tb = g_t + ((size_t)n * MID + (size_t)gi * 40) * HW;
    const float* wA = g_w3f + (size_t)co0 * 40;
#pragma unroll
    for (int cb = 0; cb < 40; cb += 20)
        k3_chunk(tb + (size_t)cb * HW, wA + cb, 40, p0, tid, tc, tr, Xs, Ws, acc);

    // relu(acc + shift3)
#pragma unroll
    for (int j = 0; j < 8; j++) {
        float bv = sh3[co0 + tr * 8 + j];
#pragma unroll
        for (int i = 0; i < 8; i++)
            acc[i][j] = fmaxf(acc[i][j] + bv, 0.f);
    }

    // ---- Phase B: shortcut (K = 240 over x, scale_sc folded) ----
    const float* xb = x + (size_t)n * CIN * HW;
    const float* wB = g_wscf + (size_t)co0 * CIN;
    for (int cb = 0; cb < 240; cb += 20)
        k3_chunk(xb + (size_t)cb * HW, wB + cb, CIN, p0, tid, tc, tr, Xs, Ws, acc);

    // ---- Epilogue: + shift_sc, store ----
#pragma unroll
    for (int j = 0; j < 8; j++) {
        int co = co0 + tr * 8 + j;
        float bv = shsc[co];
        float* op = out + ((size_t)n * COUT + co) * HW + p0 + tc * 8;
#pragma unroll
        for (int h = 0; h < 2; h++) {
            if (p0 + tc * 8 + h * 4 < HW) {
                float4 v;
                v.x = acc[h * 4 + 0][j] + bv;
                v.y = acc[h * 4 + 1][j] + bv;
                v.z = acc[h * 4 + 2][j] + bv;
                v.w = acc[h * 4 + 3][j] + bv;
                *(float4*)(op + h * 4) = v;
            }
        }
    }
}

// ---------------------------------------------------------------------------
extern "C" void kernel_launch(void* const* d_in, const int* in_sizes, int n_in,
                              void* d_out, int out_size) {
    const float* x   = (const float*)d_in[0];
    const float* w1  = (const float*)d_in[1];
    const float* s1  = (const float*)d_in[2];
    const float* b1  = (const float*)d_in[3];
    const float* w2  = (const float*)d_in[4];
    const float* s2  = (const float*)d_in[5];
    const float* b2  = (const float*)d_in[6];
    const float* w3  = (const float*)d_in[7];
    const float* s3  = (const float*)d_in[8];
    const float* b3  = (const float*)d_in[9];
    const float* wsc = (const float*)d_in[10];
    const float* ssc = (const float*)d_in[11];
    const float* bsc = (const float*)d_in[12];
    float* out = (float*)d_out;

    k_fold<<<(COUT * 40 + COUT * CIN + 255) / 256, 256>>>(w3, s3, wsc, ssc);
    k_conv1<<<dim3(13, 3, NB), 320>>>(x, w1, s1, b1);
    k_dw<<<dim3(14, MID, NB), dim3(56, 4)>>>(w2, s2, b2);
    k_main<<<dim3(25, 3, NB), 320>>>(x, b3, bsc, out);
}

// round 5
// speedup vs baseline: 1.7475x; 1.7475x over previous
#include <cuda_runtime.h>
#include <cstdint>

#define HW   3136
#define WDIM 56
#define CIN  240
#define MID  120
#define COUT 480
#define NB   32

// ---------------------------------------------------------------------------
// Scratch
// ---------------------------------------------------------------------------
__device__ float g_y1[NB * MID * HW];            // conv1+bn1+relu
__device__ float g_t [NB * MID * HW + 8 * HW];   // dw+bn2 shuffled (+8ch pad, stays 0)
// Weight fragments, tf32-converted, mma.sync lane order:
// g_fA: [mt(4)][k8(16)][t(8)][lane(32)][q(4)]   (conv3 dense-expanded, scale3 folded)
// g_fB: [mt(4)][k8(30)][t(8)][lane(32)][q(4)]   (wsc, scale_sc folded)
__device__ float g_fA[4 * 16 * 8 * 128];
__device__ float g_fB[4 * 30 * 8 * 128];

__device__ __forceinline__ float to_tf32(float x) {
    float r;
    asm("cvt.rna.tf32.f32 %0, %1;" : "=f"(r) : "f"(x));
    return r;
}

__device__ __forceinline__ void mma8(float* d, const float4& a, float b0, float b1) {
    asm volatile(
        "mma.sync.aligned.m16n8k8.row.col.f32.tf32.tf32.f32 "
        "{%0,%1,%2,%3}, {%4,%5,%6,%7}, {%8,%9}, {%0,%1,%2,%3};"
        : "+f"(d[0]), "+f"(d[1]), "+f"(d[2]), "+f"(d[3])
        : "r"(__float_as_uint(a.x)), "r"(__float_as_uint(a.y)),
          "r"(__float_as_uint(a.z)), "r"(__float_as_uint(a.w)),
          "r"(__float_as_uint(b0)), "r"(__float_as_uint(b1)));
}

// ---------------------------------------------------------------------------
// K0: fold BN into weights and pack into mma fragment order (tf32)
// A frag (q): row_local = (lane>>2) + (q&1)*8, col_k = (lane&3) + (q>>1)*4
// ---------------------------------------------------------------------------
__global__ void k_fold(const float* __restrict__ w3, const float* __restrict__ s3,
                       const float* __restrict__ wsc, const float* __restrict__ ssc) {
    int i = blockIdx.x * 256 + threadIdx.x;
    const int NA = 4 * 16 * 8 * 128;
    const int NBW = 4 * 30 * 8 * 128;
    if (i < NA) {
        int q = i & 3, lane = (i >> 2) & 31, t = (i >> 7) & 7;
        int k8 = (i >> 10) & 15, mt = i >> 14;
        int row = mt * 128 + t * 16 + (lane >> 2) + (q & 1) * 8;
        int k   = k8 * 8 + (lane & 3) + (q >> 1) * 4;
        float v = 0.f;
        if (row < COUT && k < MID) {
            int g = row / 160, lk = k - g * 40;
            if (lk >= 0 && lk < 40) v = w3[row * 40 + lk] * s3[row];
        }
        g_fA[i] = to_tf32(v);
    } else {
        int j = i - NA;
        if (j < NBW) {
            int q = j & 3, lane = (j >> 2) & 31, t = (j >> 7) & 7;
            int rest = j >> 10;
            int k8 = rest % 30, mt = rest / 30;
            int row = mt * 128 + t * 16 + (lane >> 2) + (q & 1) * 8;
            int k   = k8 * 8 + (lane & 3) + (q >> 1) * 4;
            float v = (row < COUT) ? wsc[row * CIN + k] * ssc[row] : 0.f;
            g_fB[j] = to_tf32(v);
        }
    }
}

// ---------------------------------------------------------------------------
// K1: grouped 1x1 conv (G=3) + BN + ReLU -> g_y1
// ---------------------------------------------------------------------------
__global__ __launch_bounds__(320, 2)
void k_conv1(const float* __restrict__ x, const float* __restrict__ w1,
             const float* __restrict__ s1, const float* __restrict__ b1) {
    __shared__ __align__(16) float Xs[16 * 256];
    __shared__ __align__(16) float Ws[16 * 44];

    int p0 = blockIdx.x * 256;
    int g  = blockIdx.y;
    int n  = blockIdx.z;
    int tid = threadIdx.x;
    int tc = tid & 63;
    int tr = tid >> 6;

    float acc[4][8];
#pragma unroll
    for (int i = 0; i < 4; i++)
#pragma unroll
        for (int j = 0; j < 8; j++) acc[i][j] = 0.f;

    const float* xb = x + ((size_t)n * CIN + (size_t)g * 80) * HW;

    for (int cb = 0; cb < 80; cb += 16) {
        __syncthreads();
#pragma unroll
        for (int it = 0; it < 4; it++) {
            int f = tid + it * 320;
            if (f < 1024) {
                int r = f >> 6, c4 = (f & 63) << 2;
                float4 v = make_float4(0.f, 0.f, 0.f, 0.f);
                if (p0 + c4 < HW)
                    v = *(const float4*)(xb + (size_t)(cb + r) * HW + p0 + c4);
                *(float4*)(Xs + r * 256 + c4) = v;
            }
        }
#pragma unroll
        for (int it = 0; it < 2; it++) {
            int e = tid + it * 320;
            int k = e & 15, m = e >> 4;
            Ws[k * 44 + m] = w1[(size_t)(g * 40 + m) * 80 + cb + k];
        }
        __syncthreads();
#pragma unroll
        for (int k = 0; k < 16; k++) {
            float a[4], b[8];
            *(float4*)&a[0] = *(const float4*)(Xs + k * 256 + tc * 4);
            *(float4*)&b[0] = *(const float4*)(Ws + k * 44 + tr * 8);
            *(float4*)&b[4] = *(const float4*)(Ws + k * 44 + tr * 8 + 4);
#pragma unroll
            for (int i = 0; i < 4; i++)
#pragma unroll
                for (int j = 0; j < 8; j++)
                    acc[i][j] = fmaf(a[i], b[j], acc[i][j]);
        }
    }

    if (p0 + tc * 4 < HW) {
#pragma unroll
        for (int j = 0; j < 8; j++) {
            int m = g * 40 + tr * 8 + j;
            float sc = s1[m], sh = b1[m];
            float4 v;
            v.x = fmaxf(fmaf(acc[0][j], sc, sh), 0.f);
            v.y = fmaxf(fmaf(acc[1][j], sc, sh), 0.f);
            v.z = fmaxf(fmaf(acc[2][j], sc, sh), 0.f);
            v.w = fmaxf(fmaf(acc[3][j], sc, sh), 0.f);
            *(float4*)(g_y1 + ((size_t)n * MID + m) * HW + p0 + tc * 4) = v;
        }
    }
}

// ---------------------------------------------------------------------------
// K2: depthwise 3x3 + BN2 + channel shuffle -> g_t
// ---------------------------------------------------------------------------
__global__ void k_dw(const float* __restrict__ w2, const float* __restrict__ s2,
                     const float* __restrict__ b2) {
    __shared__ float tile[6][58];
    int h0 = blockIdx.x * 4;
    int m  = blockIdx.y;
    int n  = blockIdx.z;
    int tx = threadIdx.x, ty = threadIdx.y;
    int tid = ty * 56 + tx;

    const float* src = g_y1 + ((size_t)n * MID + m) * HW;
    for (int e = tid; e < 6 * 58; e += 224) {
        int r = e / 58, c = e - r * 58;
        int hh = h0 - 1 + r, ww = c - 1;
        tile[r][c] = (hh >= 0 && hh < 56 && ww >= 0 && ww < 56)
                         ? src[hh * WDIM + ww] : 0.f;
    }
    __syncthreads();

    float wv[9];
#pragma unroll
    for (int q = 0; q < 9; q++) wv[q] = __ldg(&w2[m * 9 + q]);

    float sum = 0.f;
#pragma unroll
    for (int dy = 0; dy < 3; dy++)
#pragma unroll
        for (int dx = 0; dx < 3; dx++)
            sum = fmaf(wv[dy * 3 + dx], tile[ty + dy][tx + dx], sum);

    int cs = (m % 40) * 3 + m / 40;
    g_t[((size_t)n * MID + cs) * HW + (size_t)(h0 + ty) * WDIM + tx]
        = fmaf(s2[m], sum, b2[m]);
}

// ---------------------------------------------------------------------------
// K3 (mma.sync tf32): fused conv3 + relu(bn3) + shortcut + bn_sc + add
// CTA: 128 out-ch (of 512 padded) x 128 spatial. 8 warps = 4(M) x 2(N).
// Phase A: chunks 0..7   (K=120 pad 128, B = g_t)   -> acc
//   then acc = relu(acc + shift3)
// Phase B: chunks 8..22  (K=240,         B = x)     += acc
//   then out = acc + shift_sc
// ---------------------------------------------------------------------------
#define NCHUNK 23

__global__ __launch_bounds__(256)
void k_main_m(const float* __restrict__ x,
              const float* __restrict__ sh3, const float* __restrict__ shsc,
              float* __restrict__ out) {
    __shared__ __align__(16) float Bs[2][16][136];

    int tid = threadIdx.x;
    int wid = tid >> 5, lane = tid & 31;
    int nb = (wid & 1) * 64;          // warp N base
    int wt = (wid >> 1) * 2;          // warp's first m16-tile index (0,2,4,6)

    int p0  = blockIdx.x * 128;
    int mt  = blockIdx.y;
    int img = blockIdx.z;
    int rbase = mt * 128 + wt * 16;

    const float* srcA = g_t + (size_t)img * MID * HW;
    const float* srcB = x   + (size_t)img * CIN * HW;

    float acc[2][8][4];
#pragma unroll
    for (int t = 0; t < 2; t++)
#pragma unroll
        for (int j = 0; j < 8; j++)
#pragma unroll
            for (int q = 0; q < 4; q++) acc[t][j][q] = 0.f;

    // per-thread BN shifts: accumulator rows are (lane>>2) + h*8, h = q>>1
    float v3[2][2], vsc[2][2];
#pragma unroll
    for (int t = 0; t < 2; t++)
#pragma unroll
        for (int h = 0; h < 2; h++) {
            int co = rbase + t * 16 + (lane >> 2) + h * 8;
            bool ok = co < COUT;
            v3[t][h]  = ok ? sh3[co]  : 0.f;
            vsc[t][h] = ok ? shsc[co] : 0.f;
        }

    // ---- chunk loader: 2 float4 per thread ----
    auto ldchunk = [&](int c, float4* v) {
        const float* src; int kbase, klim;
        if (c < 8) { src = srcA; kbase = c * 16; klim = MID; }
        else       { src = srcB; kbase = (c - 8) * 16; klim = CIN; }
#pragma unroll
        for (int it = 0; it < 2; it++) {
            int f = tid + it * 256;
            int k = f >> 5, nq = f & 31;
            int kc = kbase + k, p = p0 + nq * 4;
            if (kc < klim && p < HW)
                v[it] = *(const float4*)(src + (size_t)kc * HW + p);
            else
                v[it] = make_float4(0.f, 0.f, 0.f, 0.f);
        }
    };
    auto stchunk = [&](int buf, const float4* v) {
#pragma unroll
        for (int it = 0; it < 2; it++) {
            int f = tid + it * 256;
            int k = f >> 5, nq = f & 31;
            float4 w;
            w.x = to_tf32(v[it].x); w.y = to_tf32(v[it].y);
            w.z = to_tf32(v[it].z); w.w = to_tf32(v[it].w);
            *(float4*)&Bs[buf][k][nq * 4] = w;
        }
    };

    // ---- prologue ----
    float4 ldv[2];
    ldchunk(0, ldv);
    stchunk(0, ldv);
    __syncthreads();

    for (int c = 0; c < NCHUNK; c++) {
        int buf = c & 1;

        // prefetch A fragments for this chunk (4 x LDG.128, L2-resident)
        const float* fb = (c < 8)
            ? g_fA + (size_t)((mt * 16 + c * 2) * 8) * 128
            : g_fB + (size_t)((mt * 30 + (c - 8) * 2) * 8) * 128;
        float4 af[2][2];
#pragma unroll
        for (int k8 = 0; k8 < 2; k8++)
#pragma unroll
            for (int t = 0; t < 2; t++)
                af[k8][t] = *(const float4*)(fb + (size_t)(k8 * 8 + wt + t) * 128 + lane * 4);

        // prefetch next B chunk (overlaps with compute)
        if (c + 1 < NCHUNK) ldchunk(c + 1, ldv);

        // compute
#pragma unroll
        for (int k8 = 0; k8 < 2; k8++) {
            int kr = k8 * 8 + (lane & 3);
#pragma unroll
            for (int j = 0; j < 8; j++) {
                int n = nb + j * 8 + (lane >> 2);
                float b0 = Bs[buf][kr][n];
                float b1 = Bs[buf][kr + 4][n];
                mma8(acc[0][j], af[k8][0], b0, b1);
                mma8(acc[1][j], af[k8][1], b0, b1);
            }
        }

        // phase switch: relu(acc + shift3); row half selected by q>>1
        if (c == 7) {
#pragma unroll
            for (int t = 0; t < 2; t++)
#pragma unroll
                for (int j = 0; j < 8; j++)
#pragma unroll
                    for (int q = 0; q < 4; q++)
                        acc[t][j][q] = fmaxf(acc[t][j][q] + v3[t][q >> 1], 0.f);
        }

        __syncthreads();
        if (c + 1 < NCHUNK) {
            stchunk(buf ^ 1, ldv);
            __syncthreads();
        }
    }

    // ---- epilogue: + shift_sc, store float2 pairs ----
#pragma unroll
    for (int t = 0; t < 2; t++) {
#pragma unroll
        for (int h = 0; h < 2; h++) {
            int co = rbase + t * 16 + (lane >> 2) + h * 8;
            if (co >= COUT) continue;
            float* orow = out + ((size_t)img * COUT + co) * HW;
            float bv = vsc[t][h];
#pragma unroll
            for (int j = 0; j < 8; j++) {
                int p = p0 + nb + j * 8 + 2 * (lane & 3);
                if (p < HW) {
                    float2 v;
                    v.x = acc[t][j][h * 2 + 0] + bv;
                    v.y = acc[t][j][h * 2 + 1] + bv;
                    *(float2*)(orow + p) = v;
                }
            }
        }
    }
}

// ---------------------------------------------------------------------------
extern "C" void kernel_launch(void* const* d_in, const int* in_sizes, int n_in,
                              void* d_out, int out_size) {
    const float* x   = (const float*)d_in[0];
    const float* w1  = (const float*)d_in[1];
    const float* s1  = (const float*)d_in[2];
    const float* b1  = (const float*)d_in[3];
    const float* w2  = (const float*)d_in[4];
    const float* s2  = (const float*)d_in[5];
    const float* b2  = (const float*)d_in[6];
    const float* w3  = (const float*)d_in[7];
    const float* s3  = (const float*)d_in[8];
    const float* b3  = (const float*)d_in[9];
    const float* wsc = (const float*)d_in[10];
    const float* ssc = (const float*)d_in[11];
    const float* bsc = (const float*)d_in[12];
    float* out = (float*)d_out;

    int nfold = 4 * 16 * 8 * 128 + 4 * 30 * 8 * 128;
    k_fold<<<(nfold + 255) / 256, 256>>>(w3, s3, wsc, ssc);
    k_conv1<<<dim3(13, 3, NB), 320>>>(x, w1, s1, b1);
    k_dw<<<dim3(14, MID, NB), dim3(56, 4)>>>(w2, s2, b2);
    k_main_m<<<dim3(25, 4, NB), 256>>>(x, b3, bsc, out);
}

// round 6
// speedup vs baseline: 1.9973x; 1.1429x over previous
#include <cuda_runtime.h>
#include <cuda_fp16.h>
#include <cstdint>

#define HW   3136
#define WDIM 56
#define CIN  240
#define MID  120
#define COUT 480
#define NB   32

// ---------------------------------------------------------------------------
// Scratch
// ---------------------------------------------------------------------------
__device__ float g_y1[NB * MID * HW];            // conv1+bn1+relu
__device__ float g_t [NB * MID * HW + 8 * HW];   // dw+bn2 shuffled (+8ch pad)
// fp16 weight fragments in mma.m16n8k16 lane order:
// g_fA: [mt(4)][c(8)][t(8)][lane(32)][q(4)][e(2)] halves  (conv3 dense, scale3 folded)
// g_fB: [mt(4)][c(15)][t(8)][lane(32)][q(4)][e(2)] halves (wsc, scale_sc folded)
__device__ __half g_fA[4 * 8  * 8 * 32 * 8];
__device__ __half g_fB[4 * 15 * 8 * 32 * 8];

__device__ __forceinline__ void mma16h(float* d, const uint4& a, uint32_t b0, uint32_t b1) {
    asm volatile(
        "mma.sync.aligned.m16n8k16.row.col.f32.f16.f16.f32 "
        "{%0,%1,%2,%3}, {%4,%5,%6,%7}, {%8,%9}, {%0,%1,%2,%3};"
        : "+f"(d[0]), "+f"(d[1]), "+f"(d[2]), "+f"(d[3])
        : "r"(a.x), "r"(a.y), "r"(a.z), "r"(a.w), "r"(b0), "r"(b1));
}

// ---------------------------------------------------------------------------
// K0: fold BN into weights, convert to fp16, pack into mma fragment order
// A frag reg q: row_local = (lane>>2) + (q&1)*8, k_local = (lane&3)*2 + e + (q>>1)*8
// ---------------------------------------------------------------------------
__global__ void k_fold(const float* __restrict__ w3, const float* __restrict__ s3,
                       const float* __restrict__ wsc, const float* __restrict__ ssc) {
    int i = blockIdx.x * 256 + threadIdx.x;
    const int NA = 4 * 8 * 8 * 32 * 8;       // 65536
    const int NBW = 4 * 15 * 8 * 32 * 8;     // 122880
    if (i < NA) {
        int e = i & 1, q = (i >> 1) & 3, lane = (i >> 3) & 31;
        int t = (i >> 8) & 7, c = (i >> 11) & 7, mt = i >> 14;
        int row = mt * 128 + t * 16 + (lane >> 2) + (q & 1) * 8;
        int k   = c * 16 + (lane & 3) * 2 + e + (q >> 1) * 8;
        float v = 0.f;
        if (row < COUT && k < MID) {
            int g = row / 160, lk = k - g * 40;
            if (lk >= 0 && lk < 40) v = w3[row * 40 + lk] * s3[row];
        }
        g_fA[i] = __float2half(v);
    } else {
        int j = i - NA;
        if (j < NBW) {
            int e = j & 1, q = (j >> 1) & 3, lane = (j >> 3) & 31;
            int t = (j >> 8) & 7;
            int rest = j >> 11;
            int c = rest % 15, mt = rest / 15;
            int row = mt * 128 + t * 16 + (lane >> 2) + (q & 1) * 8;
            int k   = c * 16 + (lane & 3) * 2 + e + (q >> 1) * 8;
            float v = (row < COUT) ? wsc[row * CIN + k] * ssc[row] : 0.f;
            g_fB[j] = __float2half(v);
        }
    }
}

// ---------------------------------------------------------------------------
// K1: grouped 1x1 conv (G=3) + BN + ReLU -> g_y1  (unchanged)
// ---------------------------------------------------------------------------
__global__ __launch_bounds__(320, 2)
void k_conv1(const float* __restrict__ x, const float* __restrict__ w1,
             const float* __restrict__ s1, const float* __restrict__ b1) {
    __shared__ __align__(16) float Xs[16 * 256];
    __shared__ __align__(16) float Ws[16 * 44];

    int p0 = blockIdx.x * 256;
    int g  = blockIdx.y;
    int n  = blockIdx.z;
    int tid = threadIdx.x;
    int tc = tid & 63;
    int tr = tid >> 6;

    float acc[4][8];
#pragma unroll
    for (int i = 0; i < 4; i++)
#pragma unroll
        for (int j = 0; j < 8; j++) acc[i][j] = 0.f;

    const float* xb = x + ((size_t)n * CIN + (size_t)g * 80) * HW;

    for (int cb = 0; cb < 80; cb += 16) {
        __syncthreads();
#pragma unroll
        for (int it = 0; it < 4; it++) {
            int f = tid + it * 320;
            if (f < 1024) {
                int r = f >> 6, c4 = (f & 63) << 2;
                float4 v = make_float4(0.f, 0.f, 0.f, 0.f);
                if (p0 + c4 < HW)
                    v = *(const float4*)(xb + (size_t)(cb + r) * HW + p0 + c4);
                *(float4*)(Xs + r * 256 + c4) = v;
            }
        }
#pragma unroll
        for (int it = 0; it < 2; it++) {
            int e = tid + it * 320;
            int k = e & 15, m = e >> 4;
            Ws[k * 44 + m] = w1[(size_t)(g * 40 + m) * 80 + cb + k];
        }
        __syncthreads();
#pragma unroll
        for (int k = 0; k < 16; k++) {
            float a[4], b[8];
            *(float4*)&a[0] = *(const float4*)(Xs + k * 256 + tc * 4);
            *(float4*)&b[0] = *(const float4*)(Ws + k * 44 + tr * 8);
            *(float4*)&b[4] = *(const float4*)(Ws + k * 44 + tr * 8 + 4);
#pragma unroll
            for (int i = 0; i < 4; i++)
#pragma unroll
                for (int j = 0; j < 8; j++)
                    acc[i][j] = fmaf(a[i], b[j], acc[i][j]);
        }
    }

    if (p0 + tc * 4 < HW) {
#pragma unroll
        for (int j = 0; j < 8; j++) {
            int m = g * 40 + tr * 8 + j;
            float sc = s1[m], sh = b1[m];
            float4 v;
            v.x = fmaxf(fmaf(acc[0][j], sc, sh), 0.f);
            v.y = fmaxf(fmaf(acc[1][j], sc, sh), 0.f);
            v.z = fmaxf(fmaf(acc[2][j], sc, sh), 0.f);
            v.w = fmaxf(fmaf(acc[3][j], sc, sh), 0.f);
            *(float4*)(g_y1 + ((size_t)n * MID + m) * HW + p0 + tc * 4) = v;
        }
    }
}

// ---------------------------------------------------------------------------
// K2: depthwise 3x3 + BN2 + channel shuffle -> g_t  (8 rows per CTA)
// ---------------------------------------------------------------------------
__global__ void k_dw(const float* __restrict__ w2, const float* __restrict__ s2,
                     const float* __restrict__ b2) {
    __shared__ float tile[10][58];
    int h0 = blockIdx.x * 8;
    int m  = blockIdx.y;
    int n  = blockIdx.z;
    int tx = threadIdx.x, ty = threadIdx.y;
    int tid = ty * 56 + tx;

    const float* src = g_y1 + ((size_t)n * MID + m) * HW;
    for (int e = tid; e < 10 * 58; e += 448) {
        int r = e / 58, c = e - r * 58;
        int hh = h0 - 1 + r, ww = c - 1;
        tile[r][c] = (hh >= 0 && hh < 56 && ww >= 0 && ww < 56)
                         ? src[hh * WDIM + ww] : 0.f;
    }
    __syncthreads();

    float wv[9];
#pragma unroll
    for (int q = 0; q < 9; q++) wv[q] = __ldg(&w2[m * 9 + q]);

    float sum = 0.f;
#pragma unroll
    for (int dy = 0; dy < 3; dy++)
#pragma unroll
        for (int dx = 0; dx < 3; dx++)
            sum = fmaf(wv[dy * 3 + dx], tile[ty + dy][tx + dx], sum);

    int cs = (m % 40) * 3 + m / 40;
    g_t[((size_t)n * MID + cs) * HW + (size_t)(h0 + ty) * WDIM + tx]
        = fmaf(s2[m], sum, b2[m]);
}

// ---------------------------------------------------------------------------
// K3 (mma.sync f16): fused conv3 + relu(bn3) + shortcut + bn_sc + add
// CTA: 128 out-ch x 128 spatial. 8 warps = 4(M) x 2(N). Chunk K=16.
// Phase A: chunks 0..7  (K=120 pad 128, B = g_t); then acc = relu(acc+shift3)
// Phase B: chunks 8..22 (K=240, B = x);           then out = acc + shift_sc
// ---------------------------------------------------------------------------
#define NCHUNK 23

__global__ __launch_bounds__(256)
void k_main_m(const float* __restrict__ x,
              const float* __restrict__ sh3, const float* __restrict__ shsc,
              float* __restrict__ out) {
    // B tile: [buf][k2(8)][n(128) pad->136] of half2 (packed rows k, k+1)
    __shared__ __align__(16) __half2 Bs[2][8][136];

    int tid = threadIdx.x;
    int wid = tid >> 5, lane = tid & 31;
    int nb = (wid & 1) * 64;          // warp N base
    int wt = (wid >> 1) * 2;          // warp's first m16-tile (0,2,4,6)

    int p0  = blockIdx.x * 128;
    int mt  = blockIdx.y;
    int img = blockIdx.z;
    int rbase = mt * 128 + wt * 16;

    const float* srcA = g_t + (size_t)img * MID * HW;
    const float* srcB = x   + (size_t)img * CIN * HW;

    float acc[2][8][4];
#pragma unroll
    for (int t = 0; t < 2; t++)
#pragma unroll
        for (int j = 0; j < 8; j++)
#pragma unroll
            for (int q = 0; q < 4; q++) acc[t][j][q] = 0.f;

    // BN shifts: accumulator rows are (lane>>2) + h*8, h = q>>1
    float v3[2][2], vsc[2][2];
#pragma unroll
    for (int t = 0; t < 2; t++)
#pragma unroll
        for (int h = 0; h < 2; h++) {
            int co = rbase + t * 16 + (lane >> 2) + h * 8;
            bool ok = co < COUT;
            v3[t][h]  = ok ? sh3[co]  : 0.f;
            vsc[t][h] = ok ? shsc[co] : 0.f;
        }

    // per-thread chunk-load geometry: k2 = tid>>5 (0..7), nq = tid&31
    int k2 = tid >> 5, nq = tid & 31;
    int pcol = p0 + nq * 4;
    bool pok = pcol < HW;

    // loads rows kbase+2*k2 and kbase+2*k2+1 at pcol
    auto ldchunk = [&](int c, float4* v) {
        const float* src; int kbase, klim;
        if (c < 8) { src = srcA; kbase = c * 16; klim = MID; }
        else       { src = srcB; kbase = (c - 8) * 16; klim = CIN; }
        int k = kbase + 2 * k2;
        v[0] = (pok && k     < klim) ? *(const float4*)(src + (size_t)k * HW + pcol)
                                     : make_float4(0.f, 0.f, 0.f, 0.f);
        v[1] = (pok && k + 1 < klim) ? *(const float4*)(src + (size_t)(k + 1) * HW + pcol)
                                     : make_float4(0.f, 0.f, 0.f, 0.f);
    };
    auto stchunk = [&](int buf, const float4* v) {
        __half2 h[4];
        h[0] = __floats2half2_rn(v[0].x, v[1].x);
        h[1] = __floats2half2_rn(v[0].y, v[1].y);
        h[2] = __floats2half2_rn(v[0].z, v[1].z);
        h[3] = __floats2half2_rn(v[0].w, v[1].w);
        *(uint4*)&Bs[buf][k2][nq * 4] = *(const uint4*)h;
    };

    // ---- prologue ----
    float4 ldv[2];
    ldchunk(0, ldv);
    stchunk(0, ldv);
    __syncthreads();

    const int kb0 = lane & 3;           // b0 k2-row
    const int nbl = nb + (lane >> 2);   // b n col base

    for (int c = 0; c < NCHUNK; c++) {
        int buf = c & 1;

        // A fragments: one uint4 per m16-tile (L2-resident)
        const __half* fb = (c < 8)
            ? g_fA + ((size_t)(((mt * 8)  + c)      * 8 + wt) * 32 + lane) * 8
            : g_fB + ((size_t)(((mt * 15) + (c - 8)) * 8 + wt) * 32 + lane) * 8;
        uint4 af0 = *(const uint4*)fb;
        uint4 af1 = *(const uint4*)(fb + 32 * 8);

        // prefetch next B chunk
        if (c + 1 < NCHUNK) ldchunk(c + 1, ldv);

        // compute: 8 n-tiles x 2 m-tiles
#pragma unroll
        for (int j = 0; j < 8; j++) {
            int n = nbl + j * 8;
            uint32_t b0 = *(const uint32_t*)&Bs[buf][kb0][n];
            uint32_t b1 = *(const uint32_t*)&Bs[buf][kb0 + 4][n];
            mma16h(acc[0][j], af0, b0, b1);
            mma16h(acc[1][j], af1, b0, b1);
        }

        // phase switch: relu(acc + shift3); row half = q>>1
        if (c == 7) {
#pragma unroll
            for (int t = 0; t < 2; t++)
#pragma unroll
                for (int j = 0; j < 8; j++)
#pragma unroll
                    for (int q = 0; q < 4; q++)
                        acc[t][j][q] = fmaxf(acc[t][j][q] + v3[t][q >> 1], 0.f);
        }

        if (c + 1 < NCHUNK) stchunk(buf ^ 1, ldv);
        __syncthreads();
    }

    // ---- epilogue: + shift_sc, store float2 pairs ----
#pragma unroll
    for (int t = 0; t < 2; t++) {
#pragma unroll
        for (int h = 0; h < 2; h++) {
            int co = rbase + t * 16 + (lane >> 2) + h * 8;
            if (co >= COUT) continue;
            float* orow = out + ((size_t)img * COUT + co) * HW;
            float bv = vsc[t][h];
#pragma unroll
            for (int j = 0; j < 8; j++) {
                int p = p0 + nb + j * 8 + 2 * (lane & 3);
                if (p < HW) {
                    float2 v;
                    v.x = acc[t][j][h * 2 + 0] + bv;
                    v.y = acc[t][j][h * 2 + 1] + bv;
                    *(float2*)(orow + p) = v;
                }
            }
        }
    }
}

// ---------------------------------------------------------------------------
extern "C" void kernel_launch(void* const* d_in, const int* in_sizes, int n_in,
                              void* d_out, int out_size) {
    const float* x   = (const float*)d_in[0];
    const float* w1  = (const float*)d_in[1];
    const float* s1  = (const float*)d_in[2];
    const float* b1  = (const float*)d_in[3];
    const float* w2  = (const float*)d_in[4];
    const float* s2  = (const float*)d_in[5];
    const float* b2  = (const float*)d_in[6];
    const float* w3  = (const float*)d_in[7];
    const float* s3  = (const float*)d_in[8];
    const float* b3  = (const float*)d_in[9];
    const float* wsc = (const float*)d_in[10];
    const float* ssc = (const float*)d_in[11];
    const float* bsc = (const float*)d_in[12];
    float* out = (float*)d_out;

    int nfold = 4 * 8 * 8 * 32 * 8 + 4 * 15 * 8 * 32 * 8;
    k_fold<<<(nfold + 255) / 256, 256>>>(w3, s3, wsc, ssc);
    k_conv1<<<dim3(13, 3, NB), 320>>>(x, w1, s1, b1);
    k_dw<<<dim3(7, MID, NB), dim3(56, 8)>>>(w2, s2, b2);
    k_main_m<<<dim3(25, 4, NB), 256>>>(x, b3, bsc, out);
}

// round 7
// speedup vs baseline: 2.4797x; 1.2415x over previous
#include <cuda_runtime.h>
#include <cuda_fp16.h>
#include <cstdint>

#define HW   3136
#define WDIM 56
#define CIN  240
#define MID  120
#define COUT 480
#define NB   32

// ---------------------------------------------------------------------------
// Scratch
// ---------------------------------------------------------------------------
__device__ float g_y1[NB * MID * HW];            // conv1+bn1+relu
__device__ float g_t [NB * MID * HW + 8 * HW];   // dw+bn2 shuffled (+8ch pad)
// fp16 weight fragments in mma.m16n8k16 lane order:
// g_fA: [mt(4)][c16(8)][t(8)][lane(32)][q(4)][e(2)]  (conv3 dense, scale3 folded, K=128 pad)
// g_fB: [mt(4)][c16(16)][t(8)][lane(32)][q(4)][e(2)] (wsc, scale_sc folded, K=256 pad)
__device__ __half g_fA[4 * 8  * 8 * 32 * 8];
__device__ __half g_fB[4 * 16 * 8 * 32 * 8];

__device__ __forceinline__ void mma16h(float* d, const uint4& a, uint32_t b0, uint32_t b1) {
    asm volatile(
        "mma.sync.aligned.m16n8k16.row.col.f32.f16.f16.f32 "
        "{%0,%1,%2,%3}, {%4,%5,%6,%7}, {%8,%9}, {%0,%1,%2,%3};"
        : "+f"(d[0]), "+f"(d[1]), "+f"(d[2]), "+f"(d[3])
        : "r"(a.x), "r"(a.y), "r"(a.z), "r"(a.w), "r"(b0), "r"(b1));
}

// ---------------------------------------------------------------------------
// K0: fold BN into weights, convert to fp16, pack into mma fragment order
// A frag reg q: row_local = (lane>>2) + (q&1)*8, k_local = (lane&3)*2 + e + (q>>1)*8
// ---------------------------------------------------------------------------
__global__ void k_fold(const float* __restrict__ w3, const float* __restrict__ s3,
                       const float* __restrict__ wsc, const float* __restrict__ ssc) {
    int i = blockIdx.x * 256 + threadIdx.x;
    const int NA = 4 * 8 * 8 * 32 * 8;        // 65536
    const int NBW = 4 * 16 * 8 * 32 * 8;      // 131072
    if (i < NA) {
        int e = i & 1, q = (i >> 1) & 3, lane = (i >> 3) & 31;
        int t = (i >> 8) & 7, c = (i >> 11) & 7, mt = i >> 14;
        int row = mt * 128 + t * 16 + (lane >> 2) + (q & 1) * 8;
        int k   = c * 16 + (lane & 3) * 2 + e + (q >> 1) * 8;
        float v = 0.f;
        if (row < COUT && k < MID) {
            int g = row / 160, lk = k - g * 40;
            if (lk >= 0 && lk < 40) v = w3[row * 40 + lk] * s3[row];
        }
        g_fA[i] = __float2half(v);
    } else {
        int j = i - NA;
        if (j < NBW) {
            int e = j & 1, q = (j >> 1) & 3, lane = (j >> 3) & 31;
            int t = (j >> 8) & 7;
            int rest = j >> 11;
            int c = rest & 15, mt = rest >> 4;
            int row = mt * 128 + t * 16 + (lane >> 2) + (q & 1) * 8;
            int k   = c * 16 + (lane & 3) * 2 + e + (q >> 1) * 8;
            float v = (row < COUT && k < CIN) ? wsc[row * CIN + k] * ssc[row] : 0.f;
            g_fB[j] = __float2half(v);
        }
    }
}

// ---------------------------------------------------------------------------
// K1: grouped 1x1 conv (G=3) + BN + ReLU -> g_y1  (unchanged)
// ---------------------------------------------------------------------------
__global__ __launch_bounds__(320, 2)
void k_conv1(const float* __restrict__ x, const float* __restrict__ w1,
             const float* __restrict__ s1, const float* __restrict__ b1) {
    __shared__ __align__(16) float Xs[16 * 256];
    __shared__ __align__(16) float Ws[16 * 44];

    int p0 = blockIdx.x * 256;
    int g  = blockIdx.y;
    int n  = blockIdx.z;
    int tid = threadIdx.x;
    int tc = tid & 63;
    int tr = tid >> 6;

    float acc[4][8];
#pragma unroll
    for (int i = 0; i < 4; i++)
#pragma unroll
        for (int j = 0; j < 8; j++) acc[i][j] = 0.f;

    const float* xb = x + ((size_t)n * CIN + (size_t)g * 80) * HW;

    for (int cb = 0; cb < 80; cb += 16) {
        __syncthreads();
#pragma unroll
        for (int it = 0; it < 4; it++) {
            int f = tid + it * 320;
            if (f < 1024) {
                int r = f >> 6, c4 = (f & 63) << 2;
                float4 v = make_float4(0.f, 0.f, 0.f, 0.f);
                if (p0 + c4 < HW)
                    v = *(const float4*)(xb + (size_t)(cb + r) * HW + p0 + c4);
                *(float4*)(Xs + r * 256 + c4) = v;
            }
        }
#pragma unroll
        for (int it = 0; it < 2; it++) {
            int e = tid + it * 320;
            int k = e & 15, m = e >> 4;
            Ws[k * 44 + m] = w1[(size_t)(g * 40 + m) * 80 + cb + k];
        }
        __syncthreads();
#pragma unroll
        for (int k = 0; k < 16; k++) {
            float a[4], b[8];
            *(float4*)&a[0] = *(const float4*)(Xs + k * 256 + tc * 4);
            *(float4*)&b[0] = *(const float4*)(Ws + k * 44 + tr * 8);
            *(float4*)&b[4] = *(const float4*)(Ws + k * 44 + tr * 8 + 4);
#pragma unroll
            for (int i = 0; i < 4; i++)
#pragma unroll
                for (int j = 0; j < 8; j++)
                    acc[i][j] = fmaf(a[i], b[j], acc[i][j]);
        }
    }

    if (p0 + tc * 4 < HW) {
#pragma unroll
        for (int j = 0; j < 8; j++) {
            int m = g * 40 + tr * 8 + j;
            float sc = s1[m], sh = b1[m];
            float4 v;
            v.x = fmaxf(fmaf(acc[0][j], sc, sh), 0.f);
            v.y = fmaxf(fmaf(acc[1][j], sc, sh), 0.f);
            v.z = fmaxf(fmaf(acc[2][j], sc, sh), 0.f);
            v.w = fmaxf(fmaf(acc[3][j], sc, sh), 0.f);
            *(float4*)(g_y1 + ((size_t)n * MID + m) * HW + p0 + tc * 4) = v;
        }
    }
}

// ---------------------------------------------------------------------------
// K2: depthwise 3x3 + BN2 + channel shuffle -> g_t  (8 rows per CTA)
// ---------------------------------------------------------------------------
__global__ void k_dw(const float* __restrict__ w2, const float* __restrict__ s2,
                     const float* __restrict__ b2) {
    __shared__ float tile[10][58];
    int h0 = blockIdx.x * 8;
    int m  = blockIdx.y;
    int n  = blockIdx.z;
    int tx = threadIdx.x, ty = threadIdx.y;
    int tid = ty * 56 + tx;

    const float* src = g_y1 + ((size_t)n * MID + m) * HW;
    for (int e = tid; e < 10 * 58; e += 448) {
        int r = e / 58, c = e - r * 58;
        int hh = h0 - 1 + r, ww = c - 1;
        tile[r][c] = (hh >= 0 && hh < 56 && ww >= 0 && ww < 56)
                         ? src[hh * WDIM + ww] : 0.f;
    }
    __syncthreads();

    float wv[9];
#pragma unroll
    for (int q = 0; q < 9; q++) wv[q] = __ldg(&w2[m * 9 + q]);

    float sum = 0.f;
#pragma unroll
    for (int dy = 0; dy < 3; dy++)
#pragma unroll
        for (int dx = 0; dx < 3; dx++)
            sum = fmaf(wv[dy * 3 + dx], tile[ty + dy][tx + dx], sum);

    int cs = (m % 40) * 3 + m / 40;
    g_t[((size_t)n * MID + cs) * HW + (size_t)(h0 + ty) * WDIM + tx]
        = fmaf(s2[m], sum, b2[m]);
}

// ---------------------------------------------------------------------------
// K3 (mma.sync f16, K-chunk 32): fused conv3 + relu(bn3) + shortcut + add
// CTA: 128 out-ch x 128 spatial. 8 warps = 4(M) x 2(N).
// Phase A: chunks 0..3  (K=128 pad, B = g_t); then acc = relu(acc+shift3)
// Phase B: chunks 4..11 (K=256 pad, B = x);   then out = acc + shift_sc
// ---------------------------------------------------------------------------
#define NCHUNK 12

__global__ __launch_bounds__(256)
void k_main_m(const float* __restrict__ x,
              const float* __restrict__ sh3, const float* __restrict__ shsc,
              float* __restrict__ out) {
    // B tile: [buf][k2(16)][n(128) pad->136] of half2 (rows 2*k2, 2*k2+1)
    __shared__ __align__(16) __half2 Bs[2][16][136];

    int tid = threadIdx.x;
    int wid = tid >> 5, lane = tid & 31;
    int nb = (wid & 1) * 64;          // warp N base
    int wt = (wid >> 1) * 2;          // warp's first m16-tile (0,2,4,6)

    int p0  = blockIdx.x * 128;
    int mt  = blockIdx.y;
    int img = blockIdx.z;
    int rbase = mt * 128 + wt * 16;

    const float* srcA = g_t + (size_t)img * MID * HW;
    const float* srcB = x   + (size_t)img * CIN * HW;

    float acc[2][8][4];
#pragma unroll
    for (int t = 0; t < 2; t++)
#pragma unroll
        for (int j = 0; j < 8; j++)
#pragma unroll
            for (int q = 0; q < 4; q++) acc[t][j][q] = 0.f;

    // BN shifts: accumulator rows are (lane>>2) + h*8, h = q>>1
    float v3[2][2], vsc[2][2];
#pragma unroll
    for (int t = 0; t < 2; t++)
#pragma unroll
        for (int h = 0; h < 2; h++) {
            int co = rbase + t * 16 + (lane >> 2) + h * 8;
            bool ok = co < COUT;
            v3[t][h]  = ok ? sh3[co]  : 0.f;
            vsc[t][h] = ok ? shsc[co] : 0.f;
        }

    // per-thread load geometry: covers k2-rows (tid>>5) and (tid>>5)+8
    int k2 = tid >> 5, nq = tid & 31;
    int pcol = p0 + nq * 4;
    bool pok = pcol < HW;

    // chunk c covers 32 k-rows: 2*k2+{0,1} and 2*(k2+8)+{0,1}
    auto ldchunk = [&](int c, float4* v) {
        const float* src; int kbase, klim;
        if (c < 4) { src = srcA; kbase = c * 32; klim = MID; }
        else       { src = srcB; kbase = (c - 4) * 32; klim = CIN; }
#pragma unroll
        for (int h = 0; h < 2; h++) {
            int k = kbase + 2 * (k2 + 8 * h);
            v[2*h+0] = (pok && k     < klim) ? *(const float4*)(src + (size_t)k * HW + pcol)
                                             : make_float4(0.f, 0.f, 0.f, 0.f);
            v[2*h+1] = (pok && k + 1 < klim) ? *(const float4*)(src + (size_t)(k + 1) * HW + pcol)
                                             : make_float4(0.f, 0.f, 0.f, 0.f);
        }
    };
    auto stchunk = [&](int buf, const float4* v) {
#pragma unroll
        for (int h = 0; h < 2; h++) {
            __half2 hv[4];
            hv[0] = __floats2half2_rn(v[2*h].x, v[2*h+1].x);
            hv[1] = __floats2half2_rn(v[2*h].y, v[2*h+1].y);
            hv[2] = __floats2half2_rn(v[2*h].z, v[2*h+1].z);
            hv[3] = __floats2half2_rn(v[2*h].w, v[2*h+1].w);
            *(uint4*)&Bs[buf][k2 + 8 * h][nq * 4] = *(const uint4*)hv;
        }
    };

    // ---- prologue ----
    float4 ldv[4];
    ldchunk(0, ldv);
    stchunk(0, ldv);
    __syncthreads();

    const int kb0 = lane & 3;           // base k2-row within k16 group
    const int nbl = nb + (lane >> 2);   // b n col base

    for (int c = 0; c < NCHUNK; c++) {
        int buf = c & 1;

        // A fragments: 2 k16-groups x 2 m-tiles (L2-resident)
        const __half* fb = (c < 4)
            ? g_fA + ((size_t)(((mt * 8)  + c * 2)       * 8 + wt) * 32 + lane) * 8
            : g_fB + ((size_t)(((mt * 16) + (c - 4) * 2) * 8 + wt) * 32 + lane) * 8;
        uint4 af[2][2];
#pragma unroll
        for (int g = 0; g < 2; g++)
#pragma unroll
            for (int t = 0; t < 2; t++)
                af[g][t] = *(const uint4*)(fb + ((size_t)g * 8 + t) * 32 * 8);

        // prefetch next B chunk
        if (c + 1 < NCHUNK) ldchunk(c + 1, ldv);

        // compute: 2 k16 groups x 8 n-tiles x 2 m-tiles
#pragma unroll
        for (int g = 0; g < 2; g++) {
            const __half2* brow0 = &Bs[buf][g * 8 + kb0][0];
            const __half2* brow1 = &Bs[buf][g * 8 + kb0 + 4][0];
#pragma unroll
            for (int j = 0; j < 8; j++) {
                int n = nbl + j * 8;
                uint32_t b0 = *(const uint32_t*)&brow0[n];
                uint32_t b1 = *(const uint32_t*)&brow1[n];
                mma16h(acc[0][j], af[g][0], b0, b1);
                mma16h(acc[1][j], af[g][1], b0, b1);
            }
        }

        // phase switch: relu(acc + shift3); row half = q>>1
        if (c == 3) {
#pragma unroll
            for (int t = 0; t < 2; t++)
#pragma unroll
                for (int j = 0; j < 8; j++)
#pragma unroll
                    for (int q = 0; q < 4; q++)
                        acc[t][j][q] = fmaxf(acc[t][j][q] + v3[t][q >> 1], 0.f);
        }

        if (c + 1 < NCHUNK) stchunk(buf ^ 1, ldv);
        __syncthreads();
    }

    // ---- epilogue: + shift_sc, store float2 pairs ----
#pragma unroll
    for (int t = 0; t < 2; t++) {
#pragma unroll
        for (int h = 0; h < 2; h++) {
            int co = rbase + t * 16 + (lane >> 2) + h * 8;
            if (co >= COUT) continue;
            float* orow = out + ((size_t)img * COUT + co) * HW;
            float bv = vsc[t][h];
#pragma unroll
            for (int j = 0; j < 8; j++) {
                int p = p0 + nb + j * 8 + 2 * (lane & 3);
                if (p < HW) {
                    float2 v;
                    v.x = acc[t][j][h * 2 + 0] + bv;
                    v.y = acc[t][j][h * 2 + 1] + bv;
                    *(float2*)(orow + p) = v;
                }
            }
        }
    }
}

// ---------------------------------------------------------------------------
extern "C" void kernel_launch(void* const* d_in, const int* in_sizes, int n_in,
                              void* d_out, int out_size) {
    const float* x   = (const float*)d_in[0];
    const float* w1  = (const float*)d_in[1];
    const float* s1  = (const float*)d_in[2];
    const float* b1  = (const float*)d_in[3];
    const float* w2  = (const float*)d_in[4];
    const float* s2  = (const float*)d_in[5];
    const float* b2  = (const float*)d_in[6];
    const float* w3  = (const float*)d_in[7];
    const float* s3  = (const float*)d_in[8];
    const float* b3  = (const float*)d_in[9];
    const float* wsc = (const float*)d_in[10];
    const float* ssc = (const float*)d_in[11];
    const float* bsc = (const float*)d_in[12];
    float* out = (float*)d_out;

    int nfold = 4 * 8 * 8 * 32 * 8 + 4 * 16 * 8 * 32 * 8;
    k_fold<<<(nfold + 255) / 256, 256>>>(w3, s3, wsc, ssc);
    k_conv1<<<dim3(13, 3, NB), 320>>>(x, w1, s1, b1);
    k_dw<<<dim3(7, MID, NB), dim3(56, 8)>>>(w2, s2, b2);
    k_main_m<<<dim3(25, 4, NB), 256>>>(x, b3, bsc, out);
}

// round 8
// speedup vs baseline: 2.5246x; 1.0181x over previous
#include <cuda_runtime.h>
#include <cuda_fp16.h>
#include <cstdint>

#define HW   3136
#define HWP  3200
#define WDIM 56
#define CIN  240
#define MID  120
#define COUT 480
#define NB   32

// ---------------------------------------------------------------------------
// Scratch (device globals are zero-initialized; pad regions never written)
// ---------------------------------------------------------------------------
__device__ float  g_y1[NB * MID * HW];             // conv1+bn1+relu (fp32)
__device__ __half g_th[(size_t)NB * 128 * HWP];    // dw+bn2 shuffled, half, ch pad 128
__device__ __half g_xh[(size_t)NB * 256 * HWP];    // x converted to half, ch pad 256
// fp16 weight fragments in mma.m16n8k16 lane order:
__device__ __half g_fA[4 * 8  * 8 * 32 * 8];       // conv3 dense, scale3 folded, K=128 pad
__device__ __half g_fB[4 * 16 * 8 * 32 * 8];       // wsc, scale_sc folded, K=256 pad

__device__ __forceinline__ void mma16h(float* d, const uint4& a, uint32_t b0, uint32_t b1) {
    asm volatile(
        "mma.sync.aligned.m16n8k16.row.col.f32.f16.f16.f32 "
        "{%0,%1,%2,%3}, {%4,%5,%6,%7}, {%8,%9}, {%0,%1,%2,%3};"
        : "+f"(d[0]), "+f"(d[1]), "+f"(d[2]), "+f"(d[3])
        : "r"(a.x), "r"(a.y), "r"(a.z), "r"(a.w), "r"(b0), "r"(b1));
}
__device__ __forceinline__ uint32_t smem_u32(const void* p) {
    uint32_t a;
    asm("{ .reg .u64 t; cvta.to.shared.u64 t, %1; cvt.u32.u64 %0, t; }" : "=r"(a) : "l"(p));
    return a;
}

// ---------------------------------------------------------------------------
// K0: fold BN into weights, fp16, mma fragment order
// A frag reg q: row_local = (lane>>2) + (q&1)*8, k_local = (lane&3)*2 + e + (q>>1)*8
// ---------------------------------------------------------------------------
__global__ void k_fold(const float* __restrict__ w3, const float* __restrict__ s3,
                       const float* __restrict__ wsc, const float* __restrict__ ssc) {
    int i = blockIdx.x * 256 + threadIdx.x;
    const int NA = 4 * 8 * 8 * 32 * 8;
    const int NBW = 4 * 16 * 8 * 32 * 8;
    if (i < NA) {
        int e = i & 1, q = (i >> 1) & 3, lane = (i >> 3) & 31;
        int t = (i >> 8) & 7, c = (i >> 11) & 7, mt = i >> 14;
        int row = mt * 128 + t * 16 + (lane >> 2) + (q & 1) * 8;
        int k   = c * 16 + (lane & 3) * 2 + e + (q >> 1) * 8;
        float v = 0.f;
        if (row < COUT && k < MID) {
            int g = row / 160, lk = k - g * 40;
            if (lk >= 0 && lk < 40) v = w3[row * 40 + lk] * s3[row];
        }
        g_fA[i] = __float2half(v);
    } else {
        int j = i - NA;
        if (j < NBW) {
            int e = j & 1, q = (j >> 1) & 3, lane = (j >> 3) & 31;
            int t = (j >> 8) & 7;
            int rest = j >> 11;
            int c = rest & 15, mt = rest >> 4;
            int row = mt * 128 + t * 16 + (lane >> 2) + (q & 1) * 8;
            int k   = c * 16 + (lane & 3) * 2 + e + (q >> 1) * 8;
            float v = (row < COUT && k < CIN) ? wsc[row * CIN + k] * ssc[row] : 0.f;
            g_fB[j] = __float2half(v);
        }
    }
}

// ---------------------------------------------------------------------------
// K0b: convert x (fp32, [n][240][3136]) -> g_xh (half, [n][256][3200])
// ---------------------------------------------------------------------------
__global__ void k_cvt(const float* __restrict__ x) {
    int idx = blockIdx.x * 256 + threadIdx.x;          // one float4
    const int NROW = NB * CIN, Q = HW / 4;             // 784 float4/row
    if (idx >= NROW * Q) return;
    int row = idx / Q, p4 = idx - row * Q;
    int n = row / CIN, c = row - n * CIN;
    float4 v = *(const float4*)(x + (size_t)row * HW + p4 * 4);
    __half2 h[2];
    h[0] = __floats2half2_rn(v.x, v.y);
    h[1] = __floats2half2_rn(v.z, v.w);
    *(uint2*)(g_xh + ((size_t)n * 256 + c) * HWP + p4 * 4) = *(const uint2*)h;
}

// ---------------------------------------------------------------------------
// K1: grouped 1x1 conv (G=3) + BN + ReLU -> g_y1 (fp32, unchanged)
// ---------------------------------------------------------------------------
__global__ __launch_bounds__(320, 2)
void k_conv1(const float* __restrict__ x, const float* __restrict__ w1,
             const float* __restrict__ s1, const float* __restrict__ b1) {
    __shared__ __align__(16) float Xs[16 * 256];
    __shared__ __align__(16) float Ws[16 * 44];

    int p0 = blockIdx.x * 256;
    int g  = blockIdx.y;
    int n  = blockIdx.z;
    int tid = threadIdx.x;
    int tc = tid & 63;
    int tr = tid >> 6;

    float acc[4][8];
#pragma unroll
    for (int i = 0; i < 4; i++)
#pragma unroll
        for (int j = 0; j < 8; j++) acc[i][j] = 0.f;

    const float* xb = x + ((size_t)n * CIN + (size_t)g * 80) * HW;

    for (int cb = 0; cb < 80; cb += 16) {
        __syncthreads();
#pragma unroll
        for (int it = 0; it < 4; it++) {
            int f = tid + it * 320;
            if (f < 1024) {
                int r = f >> 6, c4 = (f & 63) << 2;
                float4 v = make_float4(0.f, 0.f, 0.f, 0.f);
                if (p0 + c4 < HW)
                    v = *(const float4*)(xb + (size_t)(cb + r) * HW + p0 + c4);
                *(float4*)(Xs + r * 256 + c4) = v;
            }
        }
#pragma unroll
        for (int it = 0; it < 2; it++) {
            int e = tid + it * 320;
            int k = e & 15, m = e >> 4;
            Ws[k * 44 + m] = w1[(size_t)(g * 40 + m) * 80 + cb + k];
        }
        __syncthreads();
#pragma unroll
        for (int k = 0; k < 16; k++) {
            float a[4], b[8];
            *(float4*)&a[0] = *(const float4*)(Xs + k * 256 + tc * 4);
            *(float4*)&b[0] = *(const float4*)(Ws + k * 44 + tr * 8);
            *(float4*)&b[4] = *(const float4*)(Ws + k * 44 + tr * 8 + 4);
#pragma unroll
            for (int i = 0; i < 4; i++)
#pragma unroll
                for (int j = 0; j < 8; j++)
                    acc[i][j] = fmaf(a[i], b[j], acc[i][j]);
        }
    }

    if (p0 + tc * 4 < HW) {
#pragma unroll
        for (int j = 0; j < 8; j++) {
            int m = g * 40 + tr * 8 + j;
            float sc = s1[m], sh = b1[m];
            float4 v;
            v.x = fmaxf(fmaf(acc[0][j], sc, sh), 0.f);
            v.y = fmaxf(fmaf(acc[1][j], sc, sh), 0.f);
            v.z = fmaxf(fmaf(acc[2][j], sc, sh), 0.f);
            v.w = fmaxf(fmaf(acc[3][j], sc, sh), 0.f);
            *(float4*)(g_y1 + ((size_t)n * MID + m) * HW + p0 + tc * 4) = v;
        }
    }
}

// ---------------------------------------------------------------------------
// K2: depthwise 3x3 + BN2 + channel shuffle -> g_th (half, stride HWP)
// ---------------------------------------------------------------------------
__global__ void k_dw(const float* __restrict__ w2, const float* __restrict__ s2,
                     const float* __restrict__ b2) {
    __shared__ float tile[10][58];
    int h0 = blockIdx.x * 8;
    int m  = blockIdx.y;
    int n  = blockIdx.z;
    int tx = threadIdx.x, ty = threadIdx.y;
    int tid = ty * 56 + tx;

    const float* src = g_y1 + ((size_t)n * MID + m) * HW;
    for (int e = tid; e < 10 * 58; e += 448) {
        int r = e / 58, c = e - r * 58;
        int hh = h0 - 1 + r, ww = c - 1;
        tile[r][c] = (hh >= 0 && hh < 56 && ww >= 0 && ww < 56)
                         ? src[hh * WDIM + ww] : 0.f;
    }
    __syncthreads();

    float wv[9];
#pragma unroll
    for (int q = 0; q < 9; q++) wv[q] = __ldg(&w2[m * 9 + q]);

    float sum = 0.f;
#pragma unroll
    for (int dy = 0; dy < 3; dy++)
#pragma unroll
        for (int dx = 0; dx < 3; dx++)
            sum = fmaf(wv[dy * 3 + dx], tile[ty + dy][tx + dx], sum);

    int cs = (m % 40) * 3 + m / 40;
    g_th[((size_t)n * 128 + cs) * HWP + (size_t)(h0 + ty) * WDIM + tx]
        = __float2half(fmaf(s2[m], sum, b2[m]));
}

// ---------------------------------------------------------------------------
// K3: fp16 mma + cp.async 4-stage + ldmatrix. CTA: 128 out-ch x 128 spatial.
// Phase A: chunks 0..3  (K=128, B = g_th); then acc = relu(acc+shift3)
// Phase B: chunks 4..11 (K=256, B = g_xh); then out = acc + shift_sc
// Stage tile: 32 k-rows x 128 n halves = 8KB, swizzled for ldmatrix.
// ---------------------------------------------------------------------------
#define NCHUNK 12
#define STAGES 4

__global__ __launch_bounds__(256)
void k_main_m(const float* __restrict__ sh3, const float* __restrict__ shsc,
              float* __restrict__ out) {
    __shared__ __align__(16) char BsRaw[STAGES * 8192];
    uint32_t sbB = smem_u32(BsRaw);

    int tid = threadIdx.x;
    int wid = tid >> 5, lane = tid & 31;
    int nb = (wid & 1) * 64;          // warp N base
    int nbc = (wid & 1) * 8;          // warp n 16B-chunk base
    int wt = (wid >> 1) * 2;          // warp's first m16-tile (0,2,4,6)

    int p0  = blockIdx.x * 128;
    int mt  = blockIdx.y;
    int img = blockIdx.z;
    int rbase = mt * 128 + wt * 16;

    const __half* srcA = g_th + (size_t)img * 128 * HWP;
    const __half* srcB = g_xh + (size_t)img * 256 * HWP;

    float acc[2][8][4];
#pragma unroll
    for (int t = 0; t < 2; t++)
#pragma unroll
        for (int j = 0; j < 8; j++)
#pragma unroll
            for (int q = 0; q < 4; q++) acc[t][j][q] = 0.f;

    float v3[2][2], vsc[2][2];
#pragma unroll
    for (int t = 0; t < 2; t++)
#pragma unroll
        for (int h = 0; h < 2; h++) {
            int co = rbase + t * 16 + (lane >> 2) + h * 8;
            bool ok = co < COUT;
            v3[t][h]  = ok ? sh3[co]  : 0.f;
            vsc[t][h] = ok ? shsc[co] : 0.f;
        }

    // loader geometry: thread covers two 16B chunks per stage
    int lk  = tid >> 4;               // k row 0..15 (first half)
    int lc  = tid & 15;               // 16B chunk (n/8)

    auto issue = [&](int s) {
        const __half* src; int kbase;
        if (s < 4) { src = srcA; kbase = s * 32; }
        else       { src = srcB; kbase = (s - 4) * 32; }
        uint32_t db = sbB + (s & (STAGES - 1)) * 8192;
#pragma unroll
        for (int it = 0; it < 2; it++) {
            int k = lk + it * 16;
            const __half* gp = src + (size_t)(kbase + k) * HWP + p0 + lc * 8;
            uint32_t dst = db + k * 256 + ((lc ^ (k & 7)) << 4);
            asm volatile("cp.async.cg.shared.global [%0], [%1], 16;"
                         :: "r"(dst), "l"(gp));
        }
        asm volatile("cp.async.commit_group;");
    };

    // prologue: fill STAGES-1 stages
    issue(0); issue(1); issue(2);

    for (int c = 0; c < NCHUNK; c++) {
        if (c < NCHUNK - 2)      asm volatile("cp.async.wait_group 2;");
        else if (c == NCHUNK - 2) asm volatile("cp.async.wait_group 1;");
        else                      asm volatile("cp.async.wait_group 0;");
        __syncthreads();

        // A fragments: 2 k16-groups x 2 m-tiles (L2-resident)
        const __half* fb = (c < 4)
            ? g_fA + ((size_t)(((mt * 8)  + c * 2)       * 8 + wt) * 32 + lane) * 8
            : g_fB + ((size_t)(((mt * 16) + (c - 4) * 2) * 8 + wt) * 32 + lane) * 8;
        uint4 af[2][2];
#pragma unroll
        for (int g = 0; g < 2; g++)
#pragma unroll
            for (int t = 0; t < 2; t++)
                af[g][t] = *(const uint4*)(fb + ((size_t)g * 8 + t) * 32 * 8);

        uint32_t base = sbB + (c & (STAGES - 1)) * 8192;
        int rowl = ((lane >> 3) & 1) * 8 + (lane & 7);   // row within k16 group
        int csel = lane >> 4;                            // 0: chunk j, 1: chunk j+1

#pragma unroll
        for (int g = 0; g < 2; g++) {
            int row = g * 16 + rowl;
#pragma unroll
            for (int jp = 0; jp < 4; jp++) {
                int c16 = nbc + jp * 2 + csel;
                uint32_t addr = base + row * 256 + ((c16 ^ (row & 7)) << 4);
                uint32_t b0, b1, b2, b3;
                asm volatile(
                    "ldmatrix.sync.aligned.m8n8.x4.trans.shared.b16 {%0,%1,%2,%3}, [%4];"
                    : "=r"(b0), "=r"(b1), "=r"(b2), "=r"(b3) : "r"(addr));
                mma16h(acc[0][jp * 2],     af[g][0], b0, b1);
                mma16h(acc[1][jp * 2],     af[g][1], b0, b1);
                mma16h(acc[0][jp * 2 + 1], af[g][0], b2, b3);
                mma16h(acc[1][jp * 2 + 1], af[g][1], b2, b3);
            }
        }

        // phase switch: relu(acc + shift3); row half = q>>1
        if (c == 3) {
#pragma unroll
            for (int t = 0; t < 2; t++)
#pragma unroll
                for (int j = 0; j < 8; j++)
#pragma unroll
                    for (int q = 0; q < 4; q++)
                        acc[t][j][q] = fmaxf(acc[t][j][q] + v3[t][q >> 1], 0.f);
        }

        if (c + STAGES - 1 < NCHUNK) issue(c + STAGES - 1);
    }

    // ---- epilogue: + shift_sc, store float2 pairs ----
#pragma unroll
    for (int t = 0; t < 2; t++) {
#pragma unroll
        for (int h = 0; h < 2; h++) {
            int co = rbase + t * 16 + (lane >> 2) + h * 8;
            if (co >= COUT) continue;
            float* orow = out + ((size_t)img * COUT + co) * HW;
            float bv = vsc[t][h];
#pragma unroll
            for (int j = 0; j < 8; j++) {
                int p = p0 + nb + j * 8 + 2 * (lane & 3);
                if (p < HW) {
                    float2 v;
                    v.x = acc[t][j][h * 2 + 0] + bv;
                    v.y = acc[t][j][h * 2 + 1] + bv;
                    *(float2*)(orow + p) = v;
                }
            }
        }
    }
}

// ---------------------------------------------------------------------------
extern "C" void kernel_launch(void* const* d_in, const int* in_sizes, int n_in,
                              void* d_out, int out_size) {
    const float* x   = (const float*)d_in[0];
    const float* w1  = (const float*)d_in[1];
    const float* s1  = (const float*)d_in[2];
    const float* b1  = (const float*)d_in[3];
    const float* w2  = (const float*)d_in[4];
    const float* s2  = (const float*)d_in[5];
    const float* b2  = (const float*)d_in[6];
    const float* w3  = (const float*)d_in[7];
    const float* s3  = (const float*)d_in[8];
    const float* b3  = (const float*)d_in[9];
    const float* wsc = (const float*)d_in[10];
    const float* ssc = (const float*)d_in[11];
    const float* bsc = (const float*)d_in[12];
    float* out = (float*)d_out;

    int nfold = 4 * 8 * 8 * 32 * 8 + 4 * 16 * 8 * 32 * 8;
    k_fold<<<(nfold + 255) / 256, 256>>>(w3, s3, wsc, ssc);
    k_cvt<<<(NB * CIN * (HW / 4) + 255) / 256, 256>>>(x);
    k_conv1<<<dim3(13, 3, NB), 320>>>(x, w1, s1, b1);
    k_dw<<<dim3(7, MID, NB), dim3(56, 8)>>>(w2, s2, b2);
    k_main_m<<<dim3(25, 4, NB), 256>>>(b3, bsc, out);
}

// round 9
// speedup vs baseline: 3.0942x; 1.2256x over previous
#include <cuda_runtime.h>
#include <cuda_fp16.h>
#include <cstdint>

#define HW   3136
#define HWP  3200
#define WDIM 56
#define CIN  240
#define MID  120
#define COUT 480
#define NB   32

// ---------------------------------------------------------------------------
// Scratch (device globals are zero-initialized; pad regions never written)
// ---------------------------------------------------------------------------
__device__ float  g_y1[NB * MID * HW];             // conv1+bn1+relu (fp32)
__device__ __half g_th[(size_t)NB * 128 * HWP];    // dw+bn2 shuffled, half, ch pad 128
__device__ __half g_xh[(size_t)NB * 256 * HWP];    // x as half, ch pad 256
// fp16 weight fragments in mma.m16n8k16 lane order:
__device__ __half g_fA[4 * 8  * 8 * 32 * 8];       // conv3 dense, scale3 folded, K=128 pad
__device__ __half g_fB[4 * 16 * 8 * 32 * 8];       // wsc, scale_sc folded, K=256 pad

__device__ __forceinline__ void mma16h(float* d, const uint4& a, uint32_t b0, uint32_t b1) {
    asm volatile(
        "mma.sync.aligned.m16n8k16.row.col.f32.f16.f16.f32 "
        "{%0,%1,%2,%3}, {%4,%5,%6,%7}, {%8,%9}, {%0,%1,%2,%3};"
        : "+f"(d[0]), "+f"(d[1]), "+f"(d[2]), "+f"(d[3])
        : "r"(a.x), "r"(a.y), "r"(a.z), "r"(a.w), "r"(b0), "r"(b1));
}
__device__ __forceinline__ uint32_t smem_u32(const void* p) {
    uint32_t a;
    asm("{ .reg .u64 t; cvta.to.shared.u64 t, %1; cvt.u32.u64 %0, t; }" : "=r"(a) : "l"(p));
    return a;
}

// ---------------------------------------------------------------------------
// K0: fold BN into weights, fp16, mma fragment order
// ---------------------------------------------------------------------------
__global__ void k_fold(const float* __restrict__ w3, const float* __restrict__ s3,
                       const float* __restrict__ wsc, const float* __restrict__ ssc) {
    int i = blockIdx.x * 256 + threadIdx.x;
    const int NA = 4 * 8 * 8 * 32 * 8;
    const int NBW = 4 * 16 * 8 * 32 * 8;
    if (i < NA) {
        int e = i & 1, q = (i >> 1) & 3, lane = (i >> 3) & 31;
        int t = (i >> 8) & 7, c = (i >> 11) & 7, mt = i >> 14;
        int row = mt * 128 + t * 16 + (lane >> 2) + (q & 1) * 8;
        int k   = c * 16 + (lane & 3) * 2 + e + (q >> 1) * 8;
        float v = 0.f;
        if (row < COUT && k < MID) {
            int g = row / 160, lk = k - g * 40;
            if (lk >= 0 && lk < 40) v = w3[row * 40 + lk] * s3[row];
        }
        g_fA[i] = __float2half(v);
    } else {
        int j = i - NA;
        if (j < NBW) {
            int e = j & 1, q = (j >> 1) & 3, lane = (j >> 3) & 31;
            int t = (j >> 8) & 7;
            int rest = j >> 11;
            int c = rest & 15, mt = rest >> 4;
            int row = mt * 128 + t * 16 + (lane >> 2) + (q & 1) * 8;
            int k   = c * 16 + (lane & 3) * 2 + e + (q >> 1) * 8;
            float v = (row < COUT && k < CIN) ? wsc[row * CIN + k] * ssc[row] : 0.f;
            g_fB[j] = __float2half(v);
        }
    }
}

// ---------------------------------------------------------------------------
// K1: grouped 1x1 conv (G=3) + BN + ReLU -> g_y1; also emits g_xh (x as half)
// Each (n, c, p) of x is loaded exactly once across the grid -> safe to fold
// the fp32->fp16 conversion store here.
// ---------------------------------------------------------------------------
__global__ __launch_bounds__(320, 2)
void k_conv1(const float* __restrict__ x, const float* __restrict__ w1,
             const float* __restrict__ s1, const float* __restrict__ b1) {
    __shared__ __align__(16) float Xs[16 * 256];
    __shared__ __align__(16) float Ws[16 * 44];

    int p0 = blockIdx.x * 256;
    int g  = blockIdx.y;
    int n  = blockIdx.z;
    int tid = threadIdx.x;
    int tc = tid & 63;
    int tr = tid >> 6;

    float acc[4][8];
#pragma unroll
    for (int i = 0; i < 4; i++)
#pragma unroll
        for (int j = 0; j < 8; j++) acc[i][j] = 0.f;

    const float* xb = x + ((size_t)n * CIN + (size_t)g * 80) * HW;

    for (int cb = 0; cb < 80; cb += 16) {
        __syncthreads();
#pragma unroll
        for (int it = 0; it < 4; it++) {
            int f = tid + it * 320;
            if (f < 1024) {
                int r = f >> 6, c4 = (f & 63) << 2;
                float4 v = make_float4(0.f, 0.f, 0.f, 0.f);
                if (p0 + c4 < HW) {
                    v = *(const float4*)(xb + (size_t)(cb + r) * HW + p0 + c4);
                    // side effect: store half copy of x
                    __half2 h[2];
                    h[0] = __floats2half2_rn(v.x, v.y);
                    h[1] = __floats2half2_rn(v.z, v.w);
                    int c = g * 80 + cb + r;
                    *(uint2*)(g_xh + ((size_t)n * 256 + c) * HWP + p0 + c4)
                        = *(const uint2*)h;
                }
                *(float4*)(Xs + r * 256 + c4) = v;
            }
        }
#pragma unroll
        for (int it = 0; it < 2; it++) {
            int e = tid + it * 320;
            int k = e & 15, m = e >> 4;
            Ws[k * 44 + m] = w1[(size_t)(g * 40 + m) * 80 + cb + k];
        }
        __syncthreads();
#pragma unroll
        for (int k = 0; k < 16; k++) {
            float a[4], b[8];
            *(float4*)&a[0] = *(const float4*)(Xs + k * 256 + tc * 4);
            *(float4*)&b[0] = *(const float4*)(Ws + k * 44 + tr * 8);
            *(float4*)&b[4] = *(const float4*)(Ws + k * 44 + tr * 8 + 4);
#pragma unroll
            for (int i = 0; i < 4; i++)
#pragma unroll
                for (int j = 0; j < 8; j++)
                    acc[i][j] = fmaf(a[i], b[j], acc[i][j]);
        }
    }

    if (p0 + tc * 4 < HW) {
#pragma unroll
        for (int j = 0; j < 8; j++) {
            int m = g * 40 + tr * 8 + j;
            float sc = s1[m], sh = b1[m];
            float4 v;
            v.x = fmaxf(fmaf(acc[0][j], sc, sh), 0.f);
            v.y = fmaxf(fmaf(acc[1][j], sc, sh), 0.f);
            v.z = fmaxf(fmaf(acc[2][j], sc, sh), 0.f);
            v.w = fmaxf(fmaf(acc[3][j], sc, sh), 0.f);
            *(float4*)(g_y1 + ((size_t)n * MID + m) * HW + p0 + tc * 4) = v;
        }
    }
}

// ---------------------------------------------------------------------------
// K2: depthwise 3x3 + BN2 + channel shuffle -> g_th (half)
// One CTA per (channel, image): full 56x56 plane, tile[58][64] (shift/mask fill),
// each thread computes 7 consecutive rows with rolling 3x3 register window.
// ---------------------------------------------------------------------------
__global__ __launch_bounds__(448)
void k_dw(const float* __restrict__ w2, const float* __restrict__ s2,
          const float* __restrict__ b2) {
    __shared__ float tile[58][64];
    int m = blockIdx.x;
    int n = blockIdx.y;
    int tx = threadIdx.x, ty = threadIdx.y;
    int tid = ty * 56 + tx;

    const float* src = g_y1 + ((size_t)n * MID + m) * HW;
    for (int e = tid; e < 58 * 64; e += 448) {
        int r = e >> 6, c = e & 63;
        if (c < 58) {
            int hh = r - 1, ww = c - 1;
            tile[r][c] = (hh >= 0 && hh < 56 && ww >= 0 && ww < 56)
                             ? src[hh * WDIM + ww] : 0.f;
        }
    }
    __syncthreads();

    float wv[9];
#pragma unroll
    for (int q = 0; q < 9; q++) wv[q] = __ldg(&w2[m * 9 + q]);
    float sc = __ldg(&s2[m]), sh = __ldg(&b2[m]);

    int cs = (m % 40) * 3 + m / 40;
    __half* dst = g_th + ((size_t)n * 128 + cs) * HWP;

    int r0 = ty * 7;   // first output row for this thread
    // tile row = logical row + 1; output row `row` uses tile rows row..row+2
    float a0 = tile[r0][tx],     a1 = tile[r0][tx + 1],     a2 = tile[r0][tx + 2];
    float e0 = tile[r0 + 1][tx], e1 = tile[r0 + 1][tx + 1], e2 = tile[r0 + 1][tx + 2];
#pragma unroll
    for (int i = 0; i < 7; i++) {
        int row = r0 + i;
        float c0 = tile[row + 2][tx], c1 = tile[row + 2][tx + 1], c2 = tile[row + 2][tx + 2];
        float sum = wv[0] * a0;
        sum = fmaf(wv[1], a1, sum); sum = fmaf(wv[2], a2, sum);
        sum = fmaf(wv[3], e0, sum); sum = fmaf(wv[4], e1, sum);
        sum = fmaf(wv[5], e2, sum); sum = fmaf(wv[6], c0, sum);
        sum = fmaf(wv[7], c1, sum); sum = fmaf(wv[8], c2, sum);
        dst[row * WDIM + tx] = __float2half(fmaf(sc, sum, sh));
        a0 = e0; a1 = e1; a2 = e2;
        e0 = c0; e1 = c1; e2 = c2;
    }
}

// ---------------------------------------------------------------------------
// K3: fp16 mma + cp.async 4-stage + ldmatrix. CTA: 128 out-ch x 128 spatial.
// Phase A: chunks 0..3  (K=128, B = g_th); then acc = relu(acc+shift3)
// Phase B: chunks 4..11 (K=256, B = g_xh); then out = acc + shift_sc
// ---------------------------------------------------------------------------
#define NCHUNK 12
#define STAGES 4

__global__ __launch_bounds__(256)
void k_main_m(const float* __restrict__ sh3, const float* __restrict__ shsc,
              float* __restrict__ out) {
    __shared__ __align__(16) char BsRaw[STAGES * 8192];
    uint32_t sbB = smem_u32(BsRaw);

    int tid = threadIdx.x;
    int wid = tid >> 5, lane = tid & 31;
    int nb = (wid & 1) * 64;
    int nbc = (wid & 1) * 8;
    int wt = (wid >> 1) * 2;

    int p0  = blockIdx.x * 128;
    int mt  = blockIdx.y;
    int img = blockIdx.z;
    int rbase = mt * 128 + wt * 16;

    const __half* srcA = g_th + (size_t)img * 128 * HWP;
    const __half* srcB = g_xh + (size_t)img * 256 * HWP;

    float acc[2][8][4];
#pragma unroll
    for (int t = 0; t < 2; t++)
#pragma unroll
        for (int j = 0; j < 8; j++)
#pragma unroll
            for (int q = 0; q < 4; q++) acc[t][j][q] = 0.f;

    float v3[2][2], vsc[2][2];
#pragma unroll
    for (int t = 0; t < 2; t++)
#pragma unroll
        for (int h = 0; h < 2; h++) {
            int co = rbase + t * 16 + (lane >> 2) + h * 8;
            bool ok = co < COUT;
            v3[t][h]  = ok ? sh3[co]  : 0.f;
            vsc[t][h] = ok ? shsc[co] : 0.f;
        }

    int lk  = tid >> 4;
    int lc  = tid & 15;

    auto issue = [&](int s) {
        const __half* src; int kbase;
        if (s < 4) { src = srcA; kbase = s * 32; }
        else       { src = srcB; kbase = (s - 4) * 32; }
        uint32_t db = sbB + (s & (STAGES - 1)) * 8192;
#pragma unroll
        for (int it = 0; it < 2; it++) {
            int k = lk + it * 16;
            const __half* gp = src + (size_t)(kbase + k) * HWP + p0 + lc * 8;
            uint32_t dst = db + k * 256 + ((lc ^ (k & 7)) << 4);
            asm volatile("cp.async.cg.shared.global [%0], [%1], 16;"
                         :: "r"(dst), "l"(gp));
        }
        asm volatile("cp.async.commit_group;");
    };

    issue(0); issue(1); issue(2);

    for (int c = 0; c < NCHUNK; c++) {
        if (c < NCHUNK - 2)       asm volatile("cp.async.wait_group 2;");
        else if (c == NCHUNK - 2) asm volatile("cp.async.wait_group 1;");
        else                      asm volatile("cp.async.wait_group 0;");
        __syncthreads();

        const __half* fb = (c < 4)
            ? g_fA + ((size_t)(((mt * 8)  + c * 2)       * 8 + wt) * 32 + lane) * 8
            : g_fB + ((size_t)(((mt * 16) + (c - 4) * 2) * 8 + wt) * 32 + lane) * 8;
        uint4 af[2][2];
#pragma unroll
        for (int g = 0; g < 2; g++)
#pragma unroll
            for (int t = 0; t < 2; t++)
                af[g][t] = *(const uint4*)(fb + ((size_t)g * 8 + t) * 32 * 8);

        uint32_t base = sbB + (c & (STAGES - 1)) * 8192;
        int rowl = ((lane >> 3) & 1) * 8 + (lane & 7);
        int csel = lane >> 4;

#pragma unroll
        for (int g = 0; g < 2; g++) {
            int row = g * 16 + rowl;
#pragma unroll
            for (int jp = 0; jp < 4; jp++) {
                int c16 = nbc + jp * 2 + csel;
                uint32_t addr = base + row * 256 + ((c16 ^ (row & 7)) << 4);
                uint32_t b0, b1, b2, b3;
                asm volatile(
                    "ldmatrix.sync.aligned.m8n8.x4.trans.shared.b16 {%0,%1,%2,%3}, [%4];"
                    : "=r"(b0), "=r"(b1), "=r"(b2), "=r"(b3) : "r"(addr));
                mma16h(acc[0][jp * 2],     af[g][0], b0, b1);
                mma16h(acc[1][jp * 2],     af[g][1], b0, b1);
                mma16h(acc[0][jp * 2 + 1], af[g][0], b2, b3);
                mma16h(acc[1][jp * 2 + 1], af[g][1], b2, b3);
            }
        }

        if (c == 3) {
#pragma unroll
            for (int t = 0; t < 2; t++)
#pragma unroll
                for (int j = 0; j < 8; j++)
#pragma unroll
                    for (int q = 0; q < 4; q++)
                        acc[t][j][q] = fmaxf(acc[t][j][q] + v3[t][q >> 1], 0.f);
        }

        if (c + STAGES - 1 < NCHUNK) issue(c + STAGES - 1);
    }

    // ---- epilogue ----
#pragma unroll
    for (int t = 0; t < 2; t++) {
#pragma unroll
        for (int h = 0; h < 2; h++) {
            int co = rbase + t * 16 + (lane >> 2) + h * 8;
            if (co >= COUT) continue;
            float* orow = out + ((size_t)img * COUT + co) * HW;
            float bv = vsc[t][h];
#pragma unroll
            for (int j = 0; j < 8; j++) {
                int p = p0 + nb + j * 8 + 2 * (lane & 3);
                if (p < HW) {
                    float2 v;
                    v.x = acc[t][j][h * 2 + 0] + bv;
                    v.y = acc[t][j][h * 2 + 1] + bv;
                    *(float2*)(orow + p) = v;
                }
            }
        }
    }
}

// ---------------------------------------------------------------------------
extern "C" void kernel_launch(void* const* d_in, const int* in_sizes, int n_in,
                              void* d_out, int out_size) {
    const float* x   = (const float*)d_in[0];
    const float* w1  = (const float*)d_in[1];
    const float* s1  = (const float*)d_in[2];
    const float* b1  = (const float*)d_in[3];
    const float* w2  = (const float*)d_in[4];
    const float* s2  = (const float*)d_in[5];
    const float* b2  = (const float*)d_in[6];
    const float* w3  = (const float*)d_in[7];
    const float* s3  = (const float*)d_in[8];
    const float* b3  = (const float*)d_in[9];
    const float* wsc = (const float*)d_in[10];
    const float* ssc = (const float*)d_in[11];
    const float* bsc = (const float*)d_in[12];
    float* out = (float*)d_out;

    int nfold = 4 * 8 * 8 * 32 * 8 + 4 * 16 * 8 * 32 * 8;
    k_fold<<<(nfold + 255) / 256, 256>>>(w3, s3, wsc, ssc);
    k_conv1<<<dim3(13, 3, NB), 320>>>(x, w1, s1, b1);
    k_dw<<<dim3(MID, NB), dim3(56, 8)>>>(w2, s2, b2);
    k_main_m<<<dim3(25, 4, NB), 256>>>(b3, bsc, out);
}

// round 10
// speedup vs baseline: 3.3623x; 1.0866x over previous
#include <cuda_runtime.h>
#include <cuda_fp16.h>
#include <cstdint>

#define HW   3136
#define HWP  3200
#define WDIM 56
#define CIN  240
#define MID  120
#define COUT 480
#define NB   32

// ---------------------------------------------------------------------------
// Scratch (device globals are zero-initialized; pad regions never written)
// ---------------------------------------------------------------------------
__device__ __half g_y1h[NB * MID * HW];            // conv1+bn1+relu (half)
__device__ __half g_th[(size_t)NB * 128 * HWP];    // dw+bn2 shuffled, half, ch pad 128
__device__ __half g_xh[(size_t)NB * 256 * HWP];    // x as half, ch pad 256
// fp16 weight fragments in mma.m16n8k16 lane order:
__device__ __half g_fA[4 * 8  * 8 * 32 * 8];       // conv3 dense, scale3 folded, K=128 pad
__device__ __half g_fB[4 * 16 * 8 * 32 * 8];       // wsc, scale_sc folded, K=256 pad

__device__ __forceinline__ void mma16h(float* d, const uint4& a, uint32_t b0, uint32_t b1) {
    asm volatile(
        "mma.sync.aligned.m16n8k16.row.col.f32.f16.f16.f32 "
        "{%0,%1,%2,%3}, {%4,%5,%6,%7}, {%8,%9}, {%0,%1,%2,%3};"
        : "+f"(d[0]), "+f"(d[1]), "+f"(d[2]), "+f"(d[3])
        : "r"(a.x), "r"(a.y), "r"(a.z), "r"(a.w), "r"(b0), "r"(b1));
}
__device__ __forceinline__ uint32_t smem_u32(const void* p) {
    uint32_t a;
    asm("{ .reg .u64 t; cvta.to.shared.u64 t, %1; cvt.u32.u64 %0, t; }" : "=r"(a) : "l"(p));
    return a;
}

// ---------------------------------------------------------------------------
// K0: fold BN into weights, fp16, mma fragment order
// ---------------------------------------------------------------------------
__global__ void k_fold(const float* __restrict__ w3, const float* __restrict__ s3,
                       const float* __restrict__ wsc, const float* __restrict__ ssc) {
    int i = blockIdx.x * 256 + threadIdx.x;
    const int NA = 4 * 8 * 8 * 32 * 8;
    const int NBW = 4 * 16 * 8 * 32 * 8;
    if (i < NA) {
        int e = i & 1, q = (i >> 1) & 3, lane = (i >> 3) & 31;
        int t = (i >> 8) & 7, c = (i >> 11) & 7, mt = i >> 14;
        int row = mt * 128 + t * 16 + (lane >> 2) + (q & 1) * 8;
        int k   = c * 16 + (lane & 3) * 2 + e + (q >> 1) * 8;
        float v = 0.f;
        if (row < COUT && k < MID) {
            int g = row / 160, lk = k - g * 40;
            if (lk >= 0 && lk < 40) v = w3[row * 40 + lk] * s3[row];
        }
        g_fA[i] = __float2half(v);
    } else {
        int j = i - NA;
        if (j < NBW) {
            int e = j & 1, q = (j >> 1) & 3, lane = (j >> 3) & 31;
            int t = (j >> 8) & 7;
            int rest = j >> 11;
            int c = rest & 15, mt = rest >> 4;
            int row = mt * 128 + t * 16 + (lane >> 2) + (q & 1) * 8;
            int k   = c * 16 + (lane & 3) * 2 + e + (q >> 1) * 8;
            float v = (row < COUT && k < CIN) ? wsc[row * CIN + k] * ssc[row] : 0.f;
            g_fB[j] = __float2half(v);
        }
    }
}

// ---------------------------------------------------------------------------
// K1: grouped 1x1 conv (G=3) + BN + ReLU -> g_y1h (half); emits g_xh too
// ---------------------------------------------------------------------------
__global__ __launch_bounds__(320, 2)
void k_conv1(const float* __restrict__ x, const float* __restrict__ w1,
             const float* __restrict__ s1, const float* __restrict__ b1) {
    __shared__ __align__(16) float Xs[16 * 256];
    __shared__ __align__(16) float Ws[16 * 44];

    int p0 = blockIdx.x * 256;
    int g  = blockIdx.y;
    int n  = blockIdx.z;
    int tid = threadIdx.x;
    int tc = tid & 63;
    int tr = tid >> 6;

    float acc[4][8];
#pragma unroll
    for (int i = 0; i < 4; i++)
#pragma unroll
        for (int j = 0; j < 8; j++) acc[i][j] = 0.f;

    const float* xb = x + ((size_t)n * CIN + (size_t)g * 80) * HW;

    for (int cb = 0; cb < 80; cb += 16) {
        __syncthreads();
#pragma unroll
        for (int it = 0; it < 4; it++) {
            int f = tid + it * 320;
            if (f < 1024) {
                int r = f >> 6, c4 = (f & 63) << 2;
                float4 v = make_float4(0.f, 0.f, 0.f, 0.f);
                if (p0 + c4 < HW) {
                    v = *(const float4*)(xb + (size_t)(cb + r) * HW + p0 + c4);
                    __half2 h[2];
                    h[0] = __floats2half2_rn(v.x, v.y);
                    h[1] = __floats2half2_rn(v.z, v.w);
                    int c = g * 80 + cb + r;
                    *(uint2*)(g_xh + ((size_t)n * 256 + c) * HWP + p0 + c4)
                        = *(const uint2*)h;
                }
                *(float4*)(Xs + r * 256 + c4) = v;
            }
        }
#pragma unroll
        for (int it = 0; it < 2; it++) {
            int e = tid + it * 320;
            int k = e & 15, m = e >> 4;
            Ws[k * 44 + m] = w1[(size_t)(g * 40 + m) * 80 + cb + k];
        }
        __syncthreads();
#pragma unroll
        for (int k = 0; k < 16; k++) {
            float a[4], b[8];
            *(float4*)&a[0] = *(const float4*)(Xs + k * 256 + tc * 4);
            *(float4*)&b[0] = *(const float4*)(Ws + k * 44 + tr * 8);
            *(float4*)&b[4] = *(const float4*)(Ws + k * 44 + tr * 8 + 4);
#pragma unroll
            for (int i = 0; i < 4; i++)
#pragma unroll
                for (int j = 0; j < 8; j++)
                    acc[i][j] = fmaf(a[i], b[j], acc[i][j]);
        }
    }

    if (p0 + tc * 4 < HW) {
#pragma unroll
        for (int j = 0; j < 8; j++) {
            int m = g * 40 + tr * 8 + j;
            float sc = s1[m], sh = b1[m];
            __half2 h[2];
            h[0] = __floats2half2_rn(fmaxf(fmaf(acc[0][j], sc, sh), 0.f),
                                     fmaxf(fmaf(acc[1][j], sc, sh), 0.f));
            h[1] = __floats2half2_rn(fmaxf(fmaf(acc[2][j], sc, sh), 0.f),
                                     fmaxf(fmaf(acc[3][j], sc, sh), 0.f));
            *(uint2*)(g_y1h + ((size_t)n * MID + m) * HW + p0 + tc * 4)
                = *(const uint2*)h;
        }
    }
}

// ---------------------------------------------------------------------------
// K2: depthwise 3x3 + BN2 + channel shuffle: g_y1h (half) -> g_th (half)
// One CTA per (channel, image); 7 rows/thread rolling window.
// ---------------------------------------------------------------------------
__global__ __launch_bounds__(448)
void k_dw(const float* __restrict__ w2, const float* __restrict__ s2,
          const float* __restrict__ b2) {
    __shared__ float tile[58][64];
    int m = blockIdx.x;
    int n = blockIdx.y;
    int tx = threadIdx.x, ty = threadIdx.y;
    int tid = ty * 56 + tx;

    const __half* src = g_y1h + ((size_t)n * MID + m) * HW;
    for (int e = tid; e < 58 * 64; e += 448) {
        int r = e >> 6, c = e & 63;
        if (c < 58) {
            int hh = r - 1, ww = c - 1;
            tile[r][c] = (hh >= 0 && hh < 56 && ww >= 0 && ww < 56)
                             ? __half2float(src[hh * WDIM + ww]) : 0.f;
        }
    }
    __syncthreads();

    float wv[9];
#pragma unroll
    for (int q = 0; q < 9; q++) wv[q] = __ldg(&w2[m * 9 + q]);
    float sc = __ldg(&s2[m]), sh = __ldg(&b2[m]);

    int cs = (m % 40) * 3 + m / 40;
    __half* dst = g_th + ((size_t)n * 128 + cs) * HWP;

    int r0 = ty * 7;
    float a0 = tile[r0][tx],     a1 = tile[r0][tx + 1],     a2 = tile[r0][tx + 2];
    float e0 = tile[r0 + 1][tx], e1 = tile[r0 + 1][tx + 1], e2 = tile[r0 + 1][tx + 2];
#pragma unroll
    for (int i = 0; i < 7; i++) {
        int row = r0 + i;
        float c0 = tile[row + 2][tx], c1 = tile[row + 2][tx + 1], c2 = tile[row + 2][tx + 2];
        float sum = wv[0] * a0;
        sum = fmaf(wv[1], a1, sum); sum = fmaf(wv[2], a2, sum);
        sum = fmaf(wv[3], e0, sum); sum = fmaf(wv[4], e1, sum);
        sum = fmaf(wv[5], e2, sum); sum = fmaf(wv[6], c0, sum);
        sum = fmaf(wv[7], c1, sum); sum = fmaf(wv[8], c2, sum);
        dst[row * WDIM + tx] = __float2half(fmaf(sc, sum, sh));
        a0 = e0; a1 = e1; a2 = e2;
        e0 = c0; e1 = c1; e2 = c2;
    }
}

// ---------------------------------------------------------------------------
// K3: fp16 mma + cp.async 4-stage + ldmatrix. CTA: 128 out-ch x 128 spatial.
// Phase A (group-aware): per-mt 32k-chunk window over g_th covering only the
// k-slice its 128 rows can touch (zero-padded weights guarantee correctness):
//   mt0:[0,2) mt1:[0,3) mt2:[1,4) mt3:[2,4)
// Phase B: 8 chunks (K=256, B = g_xh). relu(+shift3) after last A chunk.
// ---------------------------------------------------------------------------
#define STAGES 4

__global__ __launch_bounds__(256)
void k_main_m(const float* __restrict__ sh3, const float* __restrict__ shsc,
              float* __restrict__ out) {
    __shared__ __align__(16) char BsRaw[STAGES * 8192];
    uint32_t sbB = smem_u32(BsRaw);

    int tid = threadIdx.x;
    int wid = tid >> 5, lane = tid & 31;
    int nb = (wid & 1) * 64;
    int nbc = (wid & 1) * 8;
    int wt = (wid >> 1) * 2;

    int p0  = blockIdx.x * 128;
    int mt  = blockIdx.y;
    int img = blockIdx.z;
    int rbase = mt * 128 + wt * 16;

    // per-mt phase-A chunk window (32-k units)
    const int sA = (mt == 0) ? 0 : (mt == 1) ? 0 : (mt == 2) ? 1 : 2;
    const int nA = (mt == 0) ? 2 : (mt == 1) ? 3 : (mt == 2) ? 3 : 2;
    const int nchunk = nA + 8;

    const __half* srcA = g_th + (size_t)img * 128 * HWP;
    const __half* srcB = g_xh + (size_t)img * 256 * HWP;

    float acc[2][8][4];
#pragma unroll
    for (int t = 0; t < 2; t++)
#pragma unroll
        for (int j = 0; j < 8; j++)
#pragma unroll
            for (int q = 0; q < 4; q++) acc[t][j][q] = 0.f;

    float v3[2][2], vsc[2][2];
#pragma unroll
    for (int t = 0; t < 2; t++)
#pragma unroll
        for (int h = 0; h < 2; h++) {
            int co = rbase + t * 16 + (lane >> 2) + h * 8;
            bool ok = co < COUT;
            v3[t][h]  = ok ? sh3[co]  : 0.f;
            vsc[t][h] = ok ? shsc[co] : 0.f;
        }

    int lk  = tid >> 4;
    int lc  = tid & 15;

    auto issue = [&](int s) {
        const __half* src; int kbase;
        if (s < nA) { src = srcA; kbase = (sA + s) * 32; }
        else        { src = srcB; kbase = (s - nA) * 32; }
        uint32_t db = sbB + (s & (STAGES - 1)) * 8192;
#pragma unroll
        for (int it = 0; it < 2; it++) {
            int k = lk + it * 16;
            const __half* gp = src + (size_t)(kbase + k) * HWP + p0 + lc * 8;
            uint32_t dst = db + k * 256 + ((lc ^ (k & 7)) << 4);
            asm volatile("cp.async.cg.shared.global [%0], [%1], 16;"
                         :: "r"(dst), "l"(gp));
        }
        asm volatile("cp.async.commit_group;");
    };

    issue(0); issue(1); issue(2);

    for (int c = 0; c < nchunk; c++) {
        if (c < nchunk - 2)       asm volatile("cp.async.wait_group 2;");
        else if (c == nchunk - 2) asm volatile("cp.async.wait_group 1;");
        else                      asm volatile("cp.async.wait_group 0;");
        __syncthreads();

        const __half* fb = (c < nA)
            ? g_fA + ((size_t)(((mt * 8)  + (sA + c) * 2)  * 8 + wt) * 32 + lane) * 8
            : g_fB + ((size_t)(((mt * 16) + (c - nA) * 2)  * 8 + wt) * 32 + lane) * 8;
        uint4 af[2][2];
#pragma unroll
        for (int g = 0; g < 2; g++)
#pragma unroll
            for (int t = 0; t < 2; t++)
                af[g][t] = *(const uint4*)(fb + ((size_t)g * 8 + t) * 32 * 8);

        uint32_t base = sbB + (c & (STAGES - 1)) * 8192;
        int rowl = ((lane >> 3) & 1) * 8 + (lane & 7);
        int csel = lane >> 4;

#pragma unroll
        for (int g = 0; g < 2; g++) {
            int row = g * 16 + rowl;
#pragma unroll
            for (int jp = 0; jp < 4; jp++) {
                int c16 = nbc + jp * 2 + csel;
                uint32_t addr = base + row * 256 + ((c16 ^ (row & 7)) << 4);
                uint32_t b0, b1, b2, b3;
                asm volatile(
                    "ldmatrix.sync.aligned.m8n8.x4.trans.shared.b16 {%0,%1,%2,%3}, [%4];"
                    : "=r"(b0), "=r"(b1), "=r"(b2), "=r"(b3) : "r"(addr));
                mma16h(acc[0][jp * 2],     af[g][0], b0, b1);
                mma16h(acc[1][jp * 2],     af[g][1], b0, b1);
                mma16h(acc[0][jp * 2 + 1], af[g][0], b2, b3);
                mma16h(acc[1][jp * 2 + 1], af[g][1], b2, b3);
            }
        }

        // relu(+shift3) after the last phase-A chunk
        if (c == nA - 1) {
#pragma unroll
            for (int t = 0; t < 2; t++)
#pragma unroll
                for (int j = 0; j < 8; j++)
#pragma unroll
                    for (int q = 0; q < 4; q++)
                        acc[t][j][q] = fmaxf(acc[t][j][q] + v3[t][q >> 1], 0.f);
        }

        if (c + STAGES - 1 < nchunk) issue(c + STAGES - 1);
    }

    // ---- epilogue ----
#pragma unroll
    for (int t = 0; t < 2; t++) {
#pragma unroll
        for (int h = 0; h < 2; h++) {
            int co = rbase + t * 16 + (lane >> 2) + h * 8;
            if (co >= COUT) continue;
            float* orow = out + ((size_t)img * COUT + co) * HW;
            float bv = vsc[t][h];
#pragma unroll
            for (int j = 0; j < 8; j++) {
                int p = p0 + nb + j * 8 + 2 * (lane & 3);
                if (p < HW) {
                    float2 v;
                    v.x = acc[t][j][h * 2 + 0] + bv;
                    v.y = acc[t][j][h * 2 + 1] + bv;
                    *(float2*)(orow + p) = v;
                }
            }
        }
    }
}

// ---------------------------------------------------------------------------
extern "C" void kernel_launch(void* const* d_in, const int* in_sizes, int n_in,
                              void* d_out, int out_size) {
    const float* x   = (const float*)d_in[0];
    const float* w1  = (const float*)d_in[1];
    const float* s1  = (const float*)d_in[2];
    const float* b1  = (const float*)d_in[3];
    const float* w2  = (const float*)d_in[4];
    const float* s2  = (const float*)d_in[5];
    const float* b2  = (const float*)d_in[6];
    const float* w3  = (const float*)d_in[7];
    const float* s3  = (const float*)d_in[8];
    const float* b3  = (const float*)d_in[9];
    const float* wsc = (const float*)d_in[10];
    const float* ssc = (const float*)d_in[11];
    const float* bsc = (const float*)d_in[12];
    float* out = (float*)d_out;

    int nfold = 4 * 8 * 8 * 32 * 8 + 4 * 16 * 8 * 32 * 8;
    k_fold<<<(nfold + 255) / 256, 256>>>(w3, s3, wsc, ssc);
    k_conv1<<<dim3(13, 3, NB), 320>>>(x, w1, s1, b1);
    k_dw<<<dim3(MID, NB), dim3(56, 8)>>>(w2, s2, b2);
    k_main_m<<<dim3(25, 4, NB), 256>>>(b3, bsc, out);
}

// round 11
// speedup vs baseline: 3.4482x; 1.0256x over previous
#include <cuda_runtime.h>
#include <cuda_fp16.h>
#include <cstdint>

#define HW   3136
#define HWP  3200
#define WDIM 56
#define CIN  240
#define MID  120
#define COUT 480
#define NB   32

// ---------------------------------------------------------------------------
// Scratch (device globals are zero-initialized; pad regions never written)
// ---------------------------------------------------------------------------
__device__ __half g_y1h[NB * MID * HW];            // conv1+bn1+relu (half)
__device__ __half g_th[(size_t)NB * 128 * HWP];    // dw+bn2 shuffled, half, ch pad 128
__device__ __half g_xh[(size_t)NB * 256 * HWP];    // x as half, ch pad 256
// fp16 weight fragments in mma.m16n8k16 lane order:
__device__ __half g_fA[4 * 8  * 8 * 32 * 8];       // conv3 dense, scale3 folded, K=128 pad
__device__ __half g_fB[4 * 16 * 8 * 32 * 8];       // wsc, scale_sc folded, K=256 pad

__device__ __forceinline__ void mma16h(float* d, const uint4& a, uint32_t b0, uint32_t b1) {
    asm volatile(
        "mma.sync.aligned.m16n8k16.row.col.f32.f16.f16.f32 "
        "{%0,%1,%2,%3}, {%4,%5,%6,%7}, {%8,%9}, {%0,%1,%2,%3};"
        : "+f"(d[0]), "+f"(d[1]), "+f"(d[2]), "+f"(d[3])
        : "r"(a.x), "r"(a.y), "r"(a.z), "r"(a.w), "r"(b0), "r"(b1));
}
__device__ __forceinline__ uint32_t smem_u32(const void* p) {
    uint32_t a;
    asm("{ .reg .u64 t; cvta.to.shared.u64 t, %1; cvt.u32.u64 %0, t; }" : "=r"(a) : "l"(p));
    return a;
}

// ---------------------------------------------------------------------------
// K0: fold BN into weights, fp16, mma fragment order
// ---------------------------------------------------------------------------
__global__ void k_fold(const float* __restrict__ w3, const float* __restrict__ s3,
                       const float* __restrict__ wsc, const float* __restrict__ ssc) {
    int i = blockIdx.x * 256 + threadIdx.x;
    const int NA = 4 * 8 * 8 * 32 * 8;
    const int NBW = 4 * 16 * 8 * 32 * 8;
    if (i < NA) {
        int e = i & 1, q = (i >> 1) & 3, lane = (i >> 3) & 31;
        int t = (i >> 8) & 7, c = (i >> 11) & 7, mt = i >> 14;
        int row = mt * 128 + t * 16 + (lane >> 2) + (q & 1) * 8;
        int k   = c * 16 + (lane & 3) * 2 + e + (q >> 1) * 8;
        float v = 0.f;
        if (row < COUT && k < MID) {
            int g = row / 160, lk = k - g * 40;
            if (lk >= 0 && lk < 40) v = w3[row * 40 + lk] * s3[row];
        }
        g_fA[i] = __float2half(v);
    } else {
        int j = i - NA;
        if (j < NBW) {
            int e = j & 1, q = (j >> 1) & 3, lane = (j >> 3) & 31;
            int t = (j >> 8) & 7;
            int rest = j >> 11;
            int c = rest & 15, mt = rest >> 4;
            int row = mt * 128 + t * 16 + (lane >> 2) + (q & 1) * 8;
            int k   = c * 16 + (lane & 3) * 2 + e + (q >> 1) * 8;
            float v = (row < COUT && k < CIN) ? wsc[row * CIN + k] * ssc[row] : 0.f;
            g_fB[j] = __float2half(v);
        }
    }
}

// ---------------------------------------------------------------------------
// K1: grouped 1x1 conv (G=3) + BN + ReLU -> g_y1h (half); emits g_xh too
// ---------------------------------------------------------------------------
__global__ __launch_bounds__(320, 2)
void k_conv1(const float* __restrict__ x, const float* __restrict__ w1,
             const float* __restrict__ s1, const float* __restrict__ b1) {
    __shared__ __align__(16) float Xs[16 * 256];
    __shared__ __align__(16) float Ws[16 * 44];

    int p0 = blockIdx.x * 256;
    int g  = blockIdx.y;
    int n  = blockIdx.z;
    int tid = threadIdx.x;
    int tc = tid & 63;
    int tr = tid >> 6;

    float acc[4][8];
#pragma unroll
    for (int i = 0; i < 4; i++)
#pragma unroll
        for (int j = 0; j < 8; j++) acc[i][j] = 0.f;

    const float* xb = x + ((size_t)n * CIN + (size_t)g * 80) * HW;

    for (int cb = 0; cb < 80; cb += 16) {
        __syncthreads();
#pragma unroll
        for (int it = 0; it < 4; it++) {
            int f = tid + it * 320;
            if (f < 1024) {
                int r = f >> 6, c4 = (f & 63) << 2;
                float4 v = make_float4(0.f, 0.f, 0.f, 0.f);
                if (p0 + c4 < HW) {
                    v = *(const float4*)(xb + (size_t)(cb + r) * HW + p0 + c4);
                    __half2 h[2];
                    h[0] = __floats2half2_rn(v.x, v.y);
                    h[1] = __floats2half2_rn(v.z, v.w);
                    int c = g * 80 + cb + r;
                    *(uint2*)(g_xh + ((size_t)n * 256 + c) * HWP + p0 + c4)
                        = *(const uint2*)h;
                }
                *(float4*)(Xs + r * 256 + c4) = v;
            }
        }
#pragma unroll
        for (int it = 0; it < 2; it++) {
            int e = tid + it * 320;
            int k = e & 15, m = e >> 4;
            Ws[k * 44 + m] = w1[(size_t)(g * 40 + m) * 80 + cb + k];
        }
        __syncthreads();
#pragma unroll
        for (int k = 0; k < 16; k++) {
            float a[4], b[8];
            *(float4*)&a[0] = *(const float4*)(Xs + k * 256 + tc * 4);
            *(float4*)&b[0] = *(const float4*)(Ws + k * 44 + tr * 8);
            *(float4*)&b[4] = *(const float4*)(Ws + k * 44 + tr * 8 + 4);
#pragma unroll
            for (int i = 0; i < 4; i++)
#pragma unroll
                for (int j = 0; j < 8; j++)
                    acc[i][j] = fmaf(a[i], b[j], acc[i][j]);
        }
    }

    if (p0 + tc * 4 < HW) {
#pragma unroll
        for (int j = 0; j < 8; j++) {
            int m = g * 40 + tr * 8 + j;
            float sc = s1[m], sh = b1[m];
            __half2 h[2];
            h[0] = __floats2half2_rn(fmaxf(fmaf(acc[0][j], sc, sh), 0.f),
                                     fmaxf(fmaf(acc[1][j], sc, sh), 0.f));
            h[1] = __floats2half2_rn(fmaxf(fmaf(acc[2][j], sc, sh), 0.f),
                                     fmaxf(fmaf(acc[3][j], sc, sh), 0.f));
            *(uint2*)(g_y1h + ((size_t)n * MID + m) * HW + p0 + tc * 4)
                = *(const uint2*)h;
        }
    }
}

// ---------------------------------------------------------------------------
// K2: depthwise 3x3 + BN2 + channel shuffle: g_y1h -> g_th (half)
// ---------------------------------------------------------------------------
__global__ __launch_bounds__(448)
void k_dw(const float* __restrict__ w2, const float* __restrict__ s2,
          const float* __restrict__ b2) {
    __shared__ float tile[58][64];
    int m = blockIdx.x;
    int n = blockIdx.y;
    int tx = threadIdx.x, ty = threadIdx.y;
    int tid = ty * 56 + tx;

    const __half* src = g_y1h + ((size_t)n * MID + m) * HW;
    for (int e = tid; e < 58 * 64; e += 448) {
        int r = e >> 6, c = e & 63;
        if (c < 58) {
            int hh = r - 1, ww = c - 1;
            tile[r][c] = (hh >= 0 && hh < 56 && ww >= 0 && ww < 56)
                             ? __half2float(src[hh * WDIM + ww]) : 0.f;
        }
    }
    __syncthreads();

    float wv[9];
#pragma unroll
    for (int q = 0; q < 9; q++) wv[q] = __ldg(&w2[m * 9 + q]);
    float sc = __ldg(&s2[m]), sh = __ldg(&b2[m]);

    int cs = (m % 40) * 3 + m / 40;
    __half* dst = g_th + ((size_t)n * 128 + cs) * HWP;

    int r0 = ty * 7;
    float a0 = tile[r0][tx],     a1 = tile[r0][tx + 1],     a2 = tile[r0][tx + 2];
    float e0 = tile[r0 + 1][tx], e1 = tile[r0 + 1][tx + 1], e2 = tile[r0 + 1][tx + 2];
#pragma unroll
    for (int i = 0; i < 7; i++) {
        int row = r0 + i;
        float c0 = tile[row + 2][tx], c1 = tile[row + 2][tx + 1], c2 = tile[row + 2][tx + 2];
        float sum = wv[0] * a0;
        sum = fmaf(wv[1], a1, sum); sum = fmaf(wv[2], a2, sum);
        sum = fmaf(wv[3], e0, sum); sum = fmaf(wv[4], e1, sum);
        sum = fmaf(wv[5], e2, sum); sum = fmaf(wv[6], c0, sum);
        sum = fmaf(wv[7], c1, sum); sum = fmaf(wv[8], c2, sum);
        dst[row * WDIM + tx] = __float2half(fmaf(sc, sum, sh));
        a0 = e0; a1 = e1; a2 = e2;
        e0 = c0; e1 = c1; e2 = c2;
    }
}

// ---------------------------------------------------------------------------
// K3: fp16 mma + cp.async, K-chunk 64 (two 32-k halves per stage), 4 stages
// (64KB dynamic smem). Grid: x=mt (fastest -> L2 B-tile sharing), y=spatial.
// Phase A windows (64-k units): sA={0,0,0,1}, nA={1,2,2,1}
// Phase B: 4 chunks of 64 (K=256). relu(+shift3) after last A chunk.
// ---------------------------------------------------------------------------
#define STAGES 4

__global__ __launch_bounds__(256)
void k_main_m(const float* __restrict__ sh3, const float* __restrict__ shsc,
              float* __restrict__ out) {
    extern __shared__ __align__(16) char BsRaw[];
    uint32_t sbB = smem_u32(BsRaw);

    int tid = threadIdx.x;
    int wid = tid >> 5, lane = tid & 31;
    int nb = (wid & 1) * 64;
    int nbc = (wid & 1) * 8;
    int wt = (wid >> 1) * 2;

    int mt  = blockIdx.x;
    int p0  = blockIdx.y * 128;
    int img = blockIdx.z;
    int rbase = mt * 128 + wt * 16;

    // phase-A chunk window in 64-k units
    const int sA = (mt == 3) ? 1 : 0;
    const int nA = (mt == 1 || mt == 2) ? 2 : 1;
    const int nchunk = nA + 4;

    const __half* srcA = g_th + (size_t)img * 128 * HWP;
    const __half* srcB = g_xh + (size_t)img * 256 * HWP;

    float acc[2][8][4];
#pragma unroll
    for (int t = 0; t < 2; t++)
#pragma unroll
        for (int j = 0; j < 8; j++)
#pragma unroll
            for (int q = 0; q < 4; q++) acc[t][j][q] = 0.f;

    float v3[2][2], vsc[2][2];
#pragma unroll
    for (int t = 0; t < 2; t++)
#pragma unroll
        for (int h = 0; h < 2; h++) {
            int co = rbase + t * 16 + (lane >> 2) + h * 8;
            bool ok = co < COUT;
            v3[t][h]  = ok ? sh3[co]  : 0.f;
            vsc[t][h] = ok ? shsc[co] : 0.f;
        }

    int lk = tid >> 4;                 // k row 0..15
    int lc = tid & 15;                 // 16B chunk col

    auto issue = [&](int s) {
        const __half* src; int kbase;
        if (s < nA) { src = srcA; kbase = (sA + s) * 64; }
        else        { src = srcB; kbase = (s - nA) * 64; }
        uint32_t db = sbB + (s & (STAGES - 1)) * 16384;
#pragma unroll
        for (int it = 0; it < 4; it++) {
            int k = lk + it * 16;      // 0..63
            const __half* gp = src + (size_t)(kbase + k) * HWP + p0 + lc * 8;
            uint32_t dst = db + k * 256 + ((lc ^ (k & 7)) << 4);
            asm volatile("cp.async.cg.shared.global [%0], [%1], 16;"
                         :: "r"(dst), "l"(gp));
        }
        asm volatile("cp.async.commit_group;");
    };

    issue(0); issue(1); issue(2);

    const int rowl = ((lane >> 3) & 1) * 8 + (lane & 7);
    const int csel = lane >> 4;

    for (int c = 0; c < nchunk; c++) {
        if (c < nchunk - 2)       asm volatile("cp.async.wait_group 2;");
        else if (c == nchunk - 2) asm volatile("cp.async.wait_group 1;");
        else                      asm volatile("cp.async.wait_group 0;");
        __syncthreads();

        uint32_t stageb = sbB + (c & (STAGES - 1)) * 16384;

#pragma unroll
        for (int h = 0; h < 2; h++) {
            int c32 = (c < nA) ? (sA + c) * 2 + h : (c - nA) * 2 + h;
            const __half* fb = (c < nA)
                ? g_fA + ((size_t)((mt * 8  + c32 * 2) * 8 + wt) * 32 + lane) * 8
                : g_fB + ((size_t)((mt * 16 + c32 * 2) * 8 + wt) * 32 + lane) * 8;
            uint4 af[2][2];
#pragma unroll
            for (int g = 0; g < 2; g++)
#pragma unroll
                for (int t = 0; t < 2; t++)
                    af[g][t] = *(const uint4*)(fb + ((size_t)g * 8 + t) * 32 * 8);

            uint32_t base = stageb + h * 8192;
#pragma unroll
            for (int g = 0; g < 2; g++) {
                int row = g * 16 + rowl;
#pragma unroll
                for (int jp = 0; jp < 4; jp++) {
                    int c16 = nbc + jp * 2 + csel;
                    uint32_t addr = base + row * 256 + ((c16 ^ (row & 7)) << 4);
                    uint32_t b0, b1, b2, b3;
                    asm volatile(
                        "ldmatrix.sync.aligned.m8n8.x4.trans.shared.b16 {%0,%1,%2,%3}, [%4];"
                        : "=r"(b0), "=r"(b1), "=r"(b2), "=r"(b3) : "r"(addr));
                    mma16h(acc[0][jp * 2],     af[g][0], b0, b1);
                    mma16h(acc[1][jp * 2],     af[g][1], b0, b1);
                    mma16h(acc[0][jp * 2 + 1], af[g][0], b2, b3);
                    mma16h(acc[1][jp * 2 + 1], af[g][1], b2, b3);
                }
            }
        }

        // relu(+shift3) after the last phase-A chunk
        if (c == nA - 1) {
#pragma unroll
            for (int t = 0; t < 2; t++)
#pragma unroll
                for (int j = 0; j < 8; j++)
#pragma unroll
                    for (int q = 0; q < 4; q++)
                        acc[t][j][q] = fmaxf(acc[t][j][q] + v3[t][q >> 1], 0.f);
        }

        if (c + STAGES - 1 < nchunk) issue(c + STAGES - 1);
    }

    // ---- epilogue ----
#pragma unroll
    for (int t = 0; t < 2; t++) {
#pragma unroll
        for (int h = 0; h < 2; h++) {
            int co = rbase + t * 16 + (lane >> 2) + h * 8;
            if (co >= COUT) continue;
            float* orow = out + ((size_t)img * COUT + co) * HW;
            float bv = vsc[t][h];
#pragma unroll
            for (int j = 0; j < 8; j++) {
                int p = p0 + nb + j * 8 + 2 * (lane & 3);
                if (p < HW) {
                    float2 v;
                    v.x = acc[t][j][h * 2 + 0] + bv;
                    v.y = acc[t][j][h * 2 + 1] + bv;
                    *(float2*)(orow + p) = v;
                }
            }
        }
    }
}

// ---------------------------------------------------------------------------
extern "C" void kernel_launch(void* const* d_in, const int* in_sizes, int n_in,
                              void* d_out, int out_size) {
    const float* x   = (const float*)d_in[0];
    const float* w1  = (const float*)d_in[1];
    const float* s1  = (const float*)d_in[2];
    const float* b1  = (const float*)d_in[3];
    const float* w2  = (const float*)d_in[4];
    const float* s2  = (const float*)d_in[5];
    const float* b2  = (const float*)d_in[6];
    const float* w3  = (const float*)d_in[7];
    const float* s3  = (const float*)d_in[8];
    const float* b3  = (const float*)d_in[9];
    const float* wsc = (const float*)d_in[10];
    const float* ssc = (const float*)d_in[11];
    const float* bsc = (const float*)d_in[12];
    float* out = (float*)d_out;

    static int smem_set = 0;
    if (!smem_set) {
        cudaFuncSetAttribute(k_main_m, cudaFuncAttributeMaxDynamicSharedMemorySize,
                             STAGES * 16384);
        smem_set = 1;
    }

    int nfold = 4 * 8 * 8 * 32 * 8 + 4 * 16 * 8 * 32 * 8;
    k_fold<<<(nfold + 255) / 256, 256>>>(w3, s3, wsc, ssc);
    k_conv1<<<dim3(13, 3, NB), 320>>>(x, w1, s1, b1);
    k_dw<<<dim3(MID, NB), dim3(56, 8)>>>(w2, s2, b2);
    k_main_m<<<dim3(4, 25, NB), 256, STAGES * 16384>>>(b3, bsc, out);
}

// round 12
// speedup vs baseline: 3.7855x; 1.0978x over previous
#include <cuda_runtime.h>
#include <cuda_fp16.h>
#include <cstdint>

#define HW   3136
#define HWP  3200
#define WDIM 56
#define CIN  240
#define MID  120
#define COUT 480
#define NB   32

// ---------------------------------------------------------------------------
// Scratch (device globals are zero-initialized; pad regions never written)
// ---------------------------------------------------------------------------
__device__ __half g_y1h[NB * MID * HW];            // conv1+bn1+relu (half)
__device__ __half g_th[(size_t)NB * 128 * HWP];    // dw+bn2 shuffled, half, ch pad 128
__device__ __half g_xh[(size_t)NB * 256 * HWP];    // x as half, ch pad 256
// fp16 weight fragments in mma.m16n8k16 lane order:
__device__ __half g_fA[4 * 8  * 8 * 32 * 8];       // conv3 dense, scale3 folded, K=128 pad
__device__ __half g_fB[4 * 16 * 8 * 32 * 8];       // wsc, scale_sc folded, K=256 pad
__device__ __half g_f1[16 * 8 * 32 * 8];           // w1 block-diag, scale1 folded, 128x256

__device__ __forceinline__ void mma16h(float* d, const uint4& a, uint32_t b0, uint32_t b1) {
    asm volatile(
        "mma.sync.aligned.m16n8k16.row.col.f32.f16.f16.f32 "
        "{%0,%1,%2,%3}, {%4,%5,%6,%7}, {%8,%9}, {%0,%1,%2,%3};"
        : "+f"(d[0]), "+f"(d[1]), "+f"(d[2]), "+f"(d[3])
        : "r"(a.x), "r"(a.y), "r"(a.z), "r"(a.w), "r"(b0), "r"(b1));
}
__device__ __forceinline__ uint32_t smem_u32(const void* p) {
    uint32_t a;
    asm("{ .reg .u64 t; cvta.to.shared.u64 t, %1; cvt.u32.u64 %0, t; }" : "=r"(a) : "l"(p));
    return a;
}

// ---------------------------------------------------------------------------
// K0: fold BN into weights, fp16, mma fragment order (three weight sets)
// A frag reg q: row_local = (lane>>2)+(q&1)*8, k_local = (lane&3)*2+e+(q>>1)*8
// ---------------------------------------------------------------------------
__global__ void k_fold(const float* __restrict__ w3, const float* __restrict__ s3,
                       const float* __restrict__ wsc, const float* __restrict__ ssc,
                       const float* __restrict__ w1, const float* __restrict__ s1) {
    int i = blockIdx.x * 256 + threadIdx.x;
    const int NA = 4 * 8 * 8 * 32 * 8;        // 65536
    const int NBW = 4 * 16 * 8 * 32 * 8;      // 131072
    const int NC = 16 * 8 * 32 * 8;           // 32768
    if (i < NA) {
        int e = i & 1, q = (i >> 1) & 3, lane = (i >> 3) & 31;
        int t = (i >> 8) & 7, c = (i >> 11) & 7, mt = i >> 14;
        int row = mt * 128 + t * 16 + (lane >> 2) + (q & 1) * 8;
        int k   = c * 16 + (lane & 3) * 2 + e + (q >> 1) * 8;
        float v = 0.f;
        if (row < COUT && k < MID) {
            int g = row / 160, lk = k - g * 40;
            if (lk >= 0 && lk < 40) v = w3[row * 40 + lk] * s3[row];
        }
        g_fA[i] = __float2half(v);
    } else if (i < NA + NBW) {
        int j = i - NA;
        int e = j & 1, q = (j >> 1) & 3, lane = (j >> 3) & 31;
        int t = (j >> 8) & 7;
        int rest = j >> 11;
        int c = rest & 15, mt = rest >> 4;
        int row = mt * 128 + t * 16 + (lane >> 2) + (q & 1) * 8;
        int k   = c * 16 + (lane & 3) * 2 + e + (q >> 1) * 8;
        float v = (row < COUT && k < CIN) ? wsc[row * CIN + k] * ssc[row] : 0.f;
        g_fB[j] = __float2half(v);
    } else {
        int l = i - NA - NBW;
        if (l < NC) {
            int e = l & 1, q = (l >> 1) & 3, lane = (l >> 3) & 31;
            int t = (l >> 8) & 7, c = l >> 11;       // 0..15
            int row = t * 16 + (lane >> 2) + (q & 1) * 8;
            int k   = c * 16 + (lane & 3) * 2 + e + (q >> 1) * 8;
            float v = 0.f;
            if (row < MID) {
                int g = row / 40, lk = k - g * 80;
                if (lk >= 0 && lk < 80) v = w1[row * 80 + lk] * s1[row];
            }
            g_f1[l] = __float2half(v);
        }
    }
}

// ---------------------------------------------------------------------------
// K0b: x (fp32 [n][240][3136]) -> g_xh (half [n][256][3200])
// ---------------------------------------------------------------------------
__global__ void k_cvt(const float* __restrict__ x) {
    int idx = blockIdx.x * 256 + threadIdx.x;
    const int Q = HW / 4;                      // 784
    if (idx >= NB * CIN * Q) return;
    int row = idx / Q, p4 = idx - row * Q;
    int n = row / CIN, c = row - n * CIN;
    float4 v = *(const float4*)(x + (size_t)row * HW + p4 * 4);
    __half2 h[2];
    h[0] = __floats2half2_rn(v.x, v.y);
    h[1] = __floats2half2_rn(v.z, v.w);
    *(uint2*)(g_xh + ((size_t)n * 256 + c) * HWP + p4 * 4) = *(const uint2*)h;
}

// ---------------------------------------------------------------------------
// K1 (tensor): grouped 1x1 conv + BN + ReLU via fp16 mma -> g_y1h
// Single 128-row m-tile (120 real). K=256 pad (240 real), 4 chunks of 64.
// Per-warp group windows: wt0 k[0,80) wt2 k[0,160) wt4 k[80,240) wt6 k[160,240)
// ---------------------------------------------------------------------------
#define STAGES 4

__global__ __launch_bounds__(256)
void k_conv1_t(const float* __restrict__ sh1) {
    extern __shared__ __align__(16) char BsRaw[];
    uint32_t sbB = smem_u32(BsRaw);

    int tid = threadIdx.x;
    int wid = tid >> 5, lane = tid & 31;
    int nb = (wid & 1) * 64;
    int nbc = (wid & 1) * 8;
    int wt = (wid >> 1) * 2;

    int p0  = blockIdx.x * 128;
    int img = blockIdx.y;

    const int klo = (wt < 4) ? 0 : (wt == 4) ? 80 : 160;
    const int khi = (wt == 0) ? 80 : (wt == 2) ? 160 : 240;

    const __half* srcB = g_xh + (size_t)img * 256 * HWP;

    float acc[2][8][4];
#pragma unroll
    for (int t = 0; t < 2; t++)
#pragma unroll
        for (int j = 0; j < 8; j++)
#pragma unroll
            for (int q = 0; q < 4; q++) acc[t][j][q] = 0.f;

    float sh1v[2][2];
#pragma unroll
    for (int t = 0; t < 2; t++)
#pragma unroll
        for (int h = 0; h < 2; h++) {
            int co = wt * 16 + t * 16 + (lane >> 2) + h * 8;
            sh1v[t][h] = (co < MID) ? sh1[co] : 0.f;
        }

    int lk = tid >> 4, lc = tid & 15;

    auto issue = [&](int s) {
        uint32_t db = sbB + (s & (STAGES - 1)) * 16384;
#pragma unroll
        for (int it = 0; it < 4; it++) {
            int k = lk + it * 16;
            const __half* gp = srcB + (size_t)(s * 64 + k) * HWP + p0 + lc * 8;
            uint32_t dst = db + k * 256 + ((lc ^ (k & 7)) << 4);
            asm volatile("cp.async.cg.shared.global [%0], [%1], 16;"
                         :: "r"(dst), "l"(gp));
        }
        asm volatile("cp.async.commit_group;");
    };

    issue(0); issue(1); issue(2);

    const int rowl = ((lane >> 3) & 1) * 8 + (lane & 7);
    const int csel = lane >> 4;

    for (int c = 0; c < 4; c++) {
        if (c < 2)       asm volatile("cp.async.wait_group 2;");
        else if (c == 2) asm volatile("cp.async.wait_group 1;");
        else             asm volatile("cp.async.wait_group 0;");
        __syncthreads();

        bool active = (c * 64 < khi) && (c * 64 + 64 > klo);
        if (active) {
            uint32_t stageb = sbB + (c & (STAGES - 1)) * 16384;
#pragma unroll
            for (int h = 0; h < 2; h++) {
                int c32 = c * 2 + h;
                const __half* fb = g_f1 + ((size_t)((c32 * 2) * 8 + wt) * 32 + lane) * 8;
                uint4 af[2][2];
#pragma unroll
                for (int g = 0; g < 2; g++)
#pragma unroll
                    for (int t = 0; t < 2; t++)
                        af[g][t] = *(const uint4*)(fb + ((size_t)g * 8 + t) * 32 * 8);

                uint32_t base = stageb + h * 8192;
#pragma unroll
                for (int g = 0; g < 2; g++) {
                    int row = g * 16 + rowl;
#pragma unroll
                    for (int jp = 0; jp < 4; jp++) {
                        int c16 = nbc + jp * 2 + csel;
                        uint32_t addr = base + row * 256 + ((c16 ^ (row & 7)) << 4);
                        uint32_t b0, b1, b2, b3;
                        asm volatile(
                            "ldmatrix.sync.aligned.m8n8.x4.trans.shared.b16 {%0,%1,%2,%3}, [%4];"
                            : "=r"(b0), "=r"(b1), "=r"(b2), "=r"(b3) : "r"(addr));
                        mma16h(acc[0][jp * 2],     af[g][0], b0, b1);
                        mma16h(acc[1][jp * 2],     af[g][1], b0, b1);
                        mma16h(acc[0][jp * 2 + 1], af[g][0], b2, b3);
                        mma16h(acc[1][jp * 2 + 1], af[g][1], b2, b3);
                    }
                }
            }
        }
        if (c + STAGES - 1 < 4) issue(c + STAGES - 1);
    }

    // epilogue: relu(acc + shift1) -> g_y1h (half2 stores)
#pragma unroll
    for (int t = 0; t < 2; t++) {
#pragma unroll
        for (int h = 0; h < 2; h++) {
            int co = wt * 16 + t * 16 + (lane >> 2) + h * 8;
            if (co >= MID) continue;
            __half* orow = g_y1h + ((size_t)img * MID + co) * HW;
            float bv = sh1v[t][h];
#pragma unroll
            for (int j = 0; j < 8; j++) {
                int p = p0 + nb + j * 8 + 2 * (lane & 3);
                if (p < HW) {
                    *(__half2*)(orow + p) = __floats2half2_rn(
                        fmaxf(acc[t][j][h * 2 + 0] + bv, 0.f),
                        fmaxf(acc[t][j][h * 2 + 1] + bv, 0.f));
                }
            }
        }
    }
}

// ---------------------------------------------------------------------------
// K2: depthwise 3x3 + BN2 + channel shuffle: g_y1h -> g_th (half)
// ---------------------------------------------------------------------------
__global__ __launch_bounds__(448)
void k_dw(const float* __restrict__ w2, const float* __restrict__ s2,
          const float* __restrict__ b2) {
    __shared__ float tile[58][64];
    int m = blockIdx.x;
    int n = blockIdx.y;
    int tx = threadIdx.x, ty = threadIdx.y;
    int tid = ty * 56 + tx;

    const __half* src = g_y1h + ((size_t)n * MID + m) * HW;
    for (int e = tid; e < 58 * 64; e += 448) {
        int r = e >> 6, c = e & 63;
        if (c < 58) {
            int hh = r - 1, ww = c - 1;
            tile[r][c] = (hh >= 0 && hh < 56 && ww >= 0 && ww < 56)
                             ? __half2float(src[hh * WDIM + ww]) : 0.f;
        }
    }
    __syncthreads();

    float wv[9];
#pragma unroll
    for (int q = 0; q < 9; q++) wv[q] = __ldg(&w2[m * 9 + q]);
    float sc = __ldg(&s2[m]), sh = __ldg(&b2[m]);

    int cs = (m % 40) * 3 + m / 40;
    __half* dst = g_th + ((size_t)n * 128 + cs) * HWP;

    int r0 = ty * 7;
    float a0 = tile[r0][tx],     a1 = tile[r0][tx + 1],     a2 = tile[r0][tx + 2];
    float e0 = tile[r0 + 1][tx], e1 = tile[r0 + 1][tx + 1], e2 = tile[r0 + 1][tx + 2];
#pragma unroll
    for (int i = 0; i < 7; i++) {
        int row = r0 + i;
        float c0 = tile[row + 2][tx], c1 = tile[row + 2][tx + 1], c2 = tile[row + 2][tx + 2];
        float sum = wv[0] * a0;
        sum = fmaf(wv[1], a1, sum); sum = fmaf(wv[2], a2, sum);
        sum = fmaf(wv[3], e0, sum); sum = fmaf(wv[4], e1, sum);
        sum = fmaf(wv[5], e2, sum); sum = fmaf(wv[6], c0, sum);
        sum = fmaf(wv[7], c1, sum); sum = fmaf(wv[8], c2, sum);
        dst[row * WDIM + tx] = __float2half(fmaf(sc, sum, sh));
        a0 = e0; a1 = e1; a2 = e2;
        e0 = c0; e1 = c1; e2 = c2;
    }
}

// ---------------------------------------------------------------------------
// K3: fused conv3 + relu(bn3) + shortcut + add (unchanged from R11)
// ---------------------------------------------------------------------------
__global__ __launch_bounds__(256)
void k_main_m(const float* __restrict__ sh3, const float* __restrict__ shsc,
              float* __restrict__ out) {
    extern __shared__ __align__(16) char BsRaw[];
    uint32_t sbB = smem_u32(BsRaw);

    int tid = threadIdx.x;
    int wid = tid >> 5, lane = tid & 31;
    int nb = (wid & 1) * 64;
    int nbc = (wid & 1) * 8;
    int wt = (wid >> 1) * 2;

    int mt  = blockIdx.x;
    int p0  = blockIdx.y * 128;
    int img = blockIdx.z;
    int rbase = mt * 128 + wt * 16;

    const int sA = (mt == 3) ? 1 : 0;
    const int nA = (mt == 1 || mt == 2) ? 2 : 1;
    const int nchunk = nA + 4;

    const __half* srcA = g_th + (size_t)img * 128 * HWP;
    const __half* srcB = g_xh + (size_t)img * 256 * HWP;

    float acc[2][8][4];
#pragma unroll
    for (int t = 0; t < 2; t++)
#pragma unroll
        for (int j = 0; j < 8; j++)
#pragma unroll
            for (int q = 0; q < 4; q++) acc[t][j][q] = 0.f;

    float v3[2][2], vsc[2][2];
#pragma unroll
    for (int t = 0; t < 2; t++)
#pragma unroll
        for (int h = 0; h < 2; h++) {
            int co = rbase + t * 16 + (lane >> 2) + h * 8;
            bool ok = co < COUT;
            v3[t][h]  = ok ? sh3[co]  : 0.f;
            vsc[t][h] = ok ? shsc[co] : 0.f;
        }

    int lk = tid >> 4, lc = tid & 15;

    auto issue = [&](int s) {
        const __half* src; int kbase;
        if (s < nA) { src = srcA; kbase = (sA + s) * 64; }
        else        { src = srcB; kbase = (s - nA) * 64; }
        uint32_t db = sbB + (s & (STAGES - 1)) * 16384;
#pragma unroll
        for (int it = 0; it < 4; it++) {
            int k = lk + it * 16;
            const __half* gp = src + (size_t)(kbase + k) * HWP + p0 + lc * 8;
            uint32_t dst = db + k * 256 + ((lc ^ (k & 7)) << 4);
            asm volatile("cp.async.cg.shared.global [%0], [%1], 16;"
                         :: "r"(dst), "l"(gp));
        }
        asm volatile("cp.async.commit_group;");
    };

    issue(0); issue(1); issue(2);

    const int rowl = ((lane >> 3) & 1) * 8 + (lane & 7);
    const int csel = lane >> 4;

    for (int c = 0; c < nchunk; c++) {
        if (c < nchunk - 2)       asm volatile("cp.async.wait_group 2;");
        else if (c == nchunk - 2) asm volatile("cp.async.wait_group 1;");
        else                      asm volatile("cp.async.wait_group 0;");
        __syncthreads();

        uint32_t stageb = sbB + (c & (STAGES - 1)) * 16384;

#pragma unroll
        for (int h = 0; h < 2; h++) {
            int c32 = (c < nA) ? (sA + c) * 2 + h : (c - nA) * 2 + h;
            const __half* fb = (c < nA)
                ? g_fA + ((size_t)((mt * 8  + c32 * 2) * 8 + wt) * 32 + lane) * 8
                : g_fB + ((size_t)((mt * 16 + c32 * 2) * 8 + wt) * 32 + lane) * 8;
            uint4 af[2][2];
#pragma unroll
            for (int g = 0; g < 2; g++)
#pragma unroll
                for (int t = 0; t < 2; t++)
                    af[g][t] = *(const uint4*)(fb + ((size_t)g * 8 + t) * 32 * 8);

            uint32_t base = stageb + h * 8192;
#pragma unroll
            for (int g = 0; g < 2; g++) {
                int row = g * 16 + rowl;
#pragma unroll
                for (int jp = 0; jp < 4; jp++) {
                    int c16 = nbc + jp * 2 + csel;
                    uint32_t addr = base + row * 256 + ((c16 ^ (row & 7)) << 4);
                    uint32_t b0, b1, b2, b3;
                    asm volatile(
                        "ldmatrix.sync.aligned.m8n8.x4.trans.shared.b16 {%0,%1,%2,%3}, [%4];"
                        : "=r"(b0), "=r"(b1), "=r"(b2), "=r"(b3) : "r"(addr));
                    mma16h(acc[0][jp * 2],     af[g][0], b0, b1);
                    mma16h(acc[1][jp * 2],     af[g][1], b0, b1);
                    mma16h(acc[0][jp * 2 + 1], af[g][0], b2, b3);
                    mma16h(acc[1][jp * 2 + 1], af[g][1], b2, b3);
                }
            }
        }

        if (c == nA - 1) {
#pragma unroll
            for (int t = 0; t < 2; t++)
#pragma unroll
                for (int j = 0; j < 8; j++)
#pragma unroll
                    for (int q = 0; q < 4; q++)
                        acc[t][j][q] = fmaxf(acc[t][j][q] + v3[t][q >> 1], 0.f);
        }

        if (c + STAGES - 1 < nchunk) issue(c + STAGES - 1);
    }

#pragma unroll
    for (int t = 0; t < 2; t++) {
#pragma unroll
        for (int h = 0; h < 2; h++) {
            int co = rbase + t * 16 + (lane >> 2) + h * 8;
            if (co >= COUT) continue;
            float* orow = out + ((size_t)img * COUT + co) * HW;
            float bv = vsc[t][h];
#pragma unroll
            for (int j = 0; j < 8; j++) {
                int p = p0 + nb + j * 8 + 2 * (lane & 3);
                if (p < HW) {
                    float2 v;
                    v.x = acc[t][j][h * 2 + 0] + bv;
                    v.y = acc[t][j][h * 2 + 1] + bv;
                    *(float2*)(orow + p) = v;
                }
            }
        }
    }
}

// ---------------------------------------------------------------------------
extern "C" void kernel_launch(void* const* d_in, const int* in_sizes, int n_in,
                              void* d_out, int out_size) {
    const float* x   = (const float*)d_in[0];
    const float* w1  = (const float*)d_in[1];
    const float* s1  = (const float*)d_in[2];
    const float* b1  = (const float*)d_in[3];
    const float* w2  = (const float*)d_in[4];
    const float* s2  = (const float*)d_in[5];
    const float* b2  = (const float*)d_in[6];
    const float* w3  = (const float*)d_in[7];
    const float* s3  = (const float*)d_in[8];
    const float* b3  = (const float*)d_in[9];
    const float* wsc = (const float*)d_in[10];
    const float* ssc = (const float*)d_in[11];
    const float* bsc = (const float*)d_in[12];
    float* out = (float*)d_out;

    static int smem_set = 0;
    if (!smem_set) {
        cudaFuncSetAttribute(k_main_m, cudaFuncAttributeMaxDynamicSharedMemorySize,
                             STAGES * 16384);
        cudaFuncSetAttribute(k_conv1_t, cudaFuncAttributeMaxDynamicSharedMemorySize,
                             STAGES * 16384);
        smem_set = 1;
    }

    int nfold = 4 * 8 * 8 * 32 * 8 + 4 * 16 * 8 * 32 * 8 + 16 * 8 * 32 * 8;
    k_fold<<<(nfold + 255) / 256, 256>>>(w3, s3, wsc, ssc, w1, s1);
    k_cvt<<<(NB * CIN * (HW / 4) + 255) / 256, 256>>>(x);
    k_conv1_t<<<dim3(25, NB), 256, STAGES * 16384>>>(b1);
    k_dw<<<dim3(MID, NB), dim3(56, 8)>>>(w2, s2, b2);
    k_main_m<<<dim3(4, 25, NB), 256, STAGES * 16384>>>(b3, bsc, out);
}

// round 13
// speedup vs baseline: 4.0464x; 1.0689x over previous
#include <cuda_runtime.h>
#include <cuda_fp16.h>
#include <cstdint>

#define HW   3136
#define HWP  3200
#define WDIM 56
#define CIN  240
#define MID  120
#define COUT 480
#define NB   32

// ---------------------------------------------------------------------------
// Scratch (device globals are zero-initialized; pad regions never written)
// ---------------------------------------------------------------------------
__device__ __half g_y1h[NB * MID * HW];            // conv1+bn1+relu (half)
__device__ __half g_th[(size_t)NB * 128 * HWP];    // dw+bn2 shuffled, half, ch pad 128
__device__ __half g_xh[(size_t)NB * 256 * HWP];    // x as half, ch pad 256
// fp16 weight fragments in mma.m16n8k16 lane order:
__device__ __half g_fA[4 * 8  * 8 * 32 * 8];       // conv3 dense, scale3 folded, K=128 pad
__device__ __half g_fB[4 * 16 * 8 * 32 * 8];       // wsc, scale_sc folded, K=256 pad
__device__ __half g_f1[16 * 8 * 32 * 8];           // w1 block-diag, scale1 folded, 128x256

__device__ __forceinline__ void mma16h(float* d, const uint4& a, uint32_t b0, uint32_t b1) {
    asm volatile(
        "mma.sync.aligned.m16n8k16.row.col.f32.f16.f16.f32 "
        "{%0,%1,%2,%3}, {%4,%5,%6,%7}, {%8,%9}, {%0,%1,%2,%3};"
        : "+f"(d[0]), "+f"(d[1]), "+f"(d[2]), "+f"(d[3])
        : "r"(a.x), "r"(a.y), "r"(a.z), "r"(a.w), "r"(b0), "r"(b1));
}
__device__ __forceinline__ uint32_t smem_u32(const void* p) {
    uint32_t a;
    asm("{ .reg .u64 t; cvta.to.shared.u64 t, %1; cvt.u32.u64 %0, t; }" : "=r"(a) : "l"(p));
    return a;
}

// ---------------------------------------------------------------------------
// K0: fold BN into weights, fp16, mma fragment order (three weight sets)
// ---------------------------------------------------------------------------
__global__ void k_fold(const float* __restrict__ w3, const float* __restrict__ s3,
                       const float* __restrict__ wsc, const float* __restrict__ ssc,
                       const float* __restrict__ w1, const float* __restrict__ s1) {
    int i = blockIdx.x * 256 + threadIdx.x;
    const int NA = 4 * 8 * 8 * 32 * 8;        // 65536
    const int NBW = 4 * 16 * 8 * 32 * 8;      // 131072
    const int NC = 16 * 8 * 32 * 8;           // 32768
    if (i < NA) {
        int e = i & 1, q = (i >> 1) & 3, lane = (i >> 3) & 31;
        int t = (i >> 8) & 7, c = (i >> 11) & 7, mt = i >> 14;
        int row = mt * 128 + t * 16 + (lane >> 2) + (q & 1) * 8;
        int k   = c * 16 + (lane & 3) * 2 + e + (q >> 1) * 8;
        float v = 0.f;
        if (row < COUT && k < MID) {
            int g = row / 160, lk = k - g * 40;
            if (lk >= 0 && lk < 40) v = w3[row * 40 + lk] * s3[row];
        }
        g_fA[i] = __float2half(v);
    } else if (i < NA + NBW) {
        int j = i - NA;
        int e = j & 1, q = (j >> 1) & 3, lane = (j >> 3) & 31;
        int t = (j >> 8) & 7;
        int rest = j >> 11;
        int c = rest & 15, mt = rest >> 4;
        int row = mt * 128 + t * 16 + (lane >> 2) + (q & 1) * 8;
        int k   = c * 16 + (lane & 3) * 2 + e + (q >> 1) * 8;
        float v = (row < COUT && k < CIN) ? wsc[row * CIN + k] * ssc[row] : 0.f;
        g_fB[j] = __float2half(v);
    } else {
        int l = i - NA - NBW;
        if (l < NC) {
            int e = l & 1, q = (l >> 1) & 3, lane = (l >> 3) & 31;
            int t = (l >> 8) & 7, c = l >> 11;       // 0..15
            int row = t * 16 + (lane >> 2) + (q & 1) * 8;
            int k   = c * 16 + (lane & 3) * 2 + e + (q >> 1) * 8;
            float v = 0.f;
            if (row < MID) {
                int g = row / 40, lk = k - g * 80;
                if (lk >= 0 && lk < 80) v = w1[row * 80 + lk] * s1[row];
            }
            g_f1[l] = __float2half(v);
        }
    }
}

// ---------------------------------------------------------------------------
// K0b: x (fp32 [n][240][3136]) -> g_xh (half [n][256][3200])
// ---------------------------------------------------------------------------
__global__ void k_cvt(const float* __restrict__ x) {
    int idx = blockIdx.x * 256 + threadIdx.x;
    const int Q = HW / 4;                      // 784
    if (idx >= NB * CIN * Q) return;
    int row = idx / Q, p4 = idx - row * Q;
    int n = row / CIN, c = row - n * CIN;
    float4 v = *(const float4*)(x + (size_t)row * HW + p4 * 4);
    __half2 h[2];
    h[0] = __floats2half2_rn(v.x, v.y);
    h[1] = __floats2half2_rn(v.z, v.w);
    *(uint2*)(g_xh + ((size_t)n * 256 + c) * HWP + p4 * 4) = *(const uint2*)h;
}

// ---------------------------------------------------------------------------
// K1 (tensor): grouped 1x1 conv + BN + ReLU via fp16 mma -> g_y1h
// ---------------------------------------------------------------------------
#define STAGES 4

__global__ __launch_bounds__(256)
void k_conv1_t(const float* __restrict__ sh1) {
    extern __shared__ __align__(16) char BsRaw[];
    uint32_t sbB = smem_u32(BsRaw);

    int tid = threadIdx.x;
    int wid = tid >> 5, lane = tid & 31;
    int nb = (wid & 1) * 64;
    int nbc = (wid & 1) * 8;
    int wt = (wid >> 1) * 2;

    int p0  = blockIdx.x * 128;
    int img = blockIdx.y;

    const int klo = (wt < 4) ? 0 : (wt == 4) ? 80 : 160;
    const int khi = (wt == 0) ? 80 : (wt == 2) ? 160 : 240;

    const __half* srcB = g_xh + (size_t)img * 256 * HWP;

    float acc[2][8][4];
#pragma unroll
    for (int t = 0; t < 2; t++)
#pragma unroll
        for (int j = 0; j < 8; j++)
#pragma unroll
            for (int q = 0; q < 4; q++) acc[t][j][q] = 0.f;

    float sh1v[2][2];
#pragma unroll
    for (int t = 0; t < 2; t++)
#pragma unroll
        for (int h = 0; h < 2; h++) {
            int co = wt * 16 + t * 16 + (lane >> 2) + h * 8;
            sh1v[t][h] = (co < MID) ? sh1[co] : 0.f;
        }

    int lk = tid >> 4, lc = tid & 15;

    auto issue = [&](int s) {
        uint32_t db = sbB + (s & (STAGES - 1)) * 16384;
#pragma unroll
        for (int it = 0; it < 4; it++) {
            int k = lk + it * 16;
            const __half* gp = srcB + (size_t)(s * 64 + k) * HWP + p0 + lc * 8;
            uint32_t dst = db + k * 256 + ((lc ^ (k & 7)) << 4);
            asm volatile("cp.async.cg.shared.global [%0], [%1], 16;"
                         :: "r"(dst), "l"(gp));
        }
        asm volatile("cp.async.commit_group;");
    };

    issue(0); issue(1); issue(2);

    const int rowl = ((lane >> 3) & 1) * 8 + (lane & 7);
    const int csel = lane >> 4;

    for (int c = 0; c < 4; c++) {
        if (c < 2)       asm volatile("cp.async.wait_group 2;");
        else if (c == 2) asm volatile("cp.async.wait_group 1;");
        else             asm volatile("cp.async.wait_group 0;");
        __syncthreads();

        bool active = (c * 64 < khi) && (c * 64 + 64 > klo);
        if (active) {
            uint32_t stageb = sbB + (c & (STAGES - 1)) * 16384;
#pragma unroll
            for (int h = 0; h < 2; h++) {
                int c32 = c * 2 + h;
                const __half* fb = g_f1 + ((size_t)((c32 * 2) * 8 + wt) * 32 + lane) * 8;
                uint4 af[2][2];
#pragma unroll
                for (int g = 0; g < 2; g++)
#pragma unroll
                    for (int t = 0; t < 2; t++)
                        af[g][t] = *(const uint4*)(fb + ((size_t)g * 8 + t) * 32 * 8);

                uint32_t base = stageb + h * 8192;
#pragma unroll
                for (int g = 0; g < 2; g++) {
                    int row = g * 16 + rowl;
#pragma unroll
                    for (int jp = 0; jp < 4; jp++) {
                        int c16 = nbc + jp * 2 + csel;
                        uint32_t addr = base + row * 256 + ((c16 ^ (row & 7)) << 4);
                        uint32_t b0, b1, b2, b3;
                        asm volatile(
                            "ldmatrix.sync.aligned.m8n8.x4.trans.shared.b16 {%0,%1,%2,%3}, [%4];"
                            : "=r"(b0), "=r"(b1), "=r"(b2), "=r"(b3) : "r"(addr));
                        mma16h(acc[0][jp * 2],     af[g][0], b0, b1);
                        mma16h(acc[1][jp * 2],     af[g][1], b0, b1);
                        mma16h(acc[0][jp * 2 + 1], af[g][0], b2, b3);
                        mma16h(acc[1][jp * 2 + 1], af[g][1], b2, b3);
                    }
                }
            }
        }
        if (c + STAGES - 1 < 4) issue(c + STAGES - 1);
    }

    // epilogue: relu(acc + shift1) -> g_y1h (half2 stores)
#pragma unroll
    for (int t = 0; t < 2; t++) {
#pragma unroll
        for (int h = 0; h < 2; h++) {
            int co = wt * 16 + t * 16 + (lane >> 2) + h * 8;
            if (co >= MID) continue;
            __half* orow = g_y1h + ((size_t)img * MID + co) * HW;
            float bv = sh1v[t][h];
#pragma unroll
            for (int j = 0; j < 8; j++) {
                int p = p0 + nb + j * 8 + 2 * (lane & 3);
                if (p < HW) {
                    *(__half2*)(orow + p) = __floats2half2_rn(
                        fmaxf(acc[t][j][h * 2 + 0] + bv, 0.f),
                        fmaxf(acc[t][j][h * 2 + 1] + bv, 0.f));
                }
            }
        }
    }
}

// ---------------------------------------------------------------------------
// K2: depthwise 3x3 + BN2 + channel shuffle: g_y1h -> g_th (half)
// Vectorized fill: src col c -> tile col c+8 (16B-aligned uint4 rows),
// halo zeroed explicitly (rows 0,57; cols 7,64). 7 rows/thread rolling window.
// ---------------------------------------------------------------------------
__global__ __launch_bounds__(448)
void k_dw(const float* __restrict__ w2, const float* __restrict__ s2,
          const float* __restrict__ b2) {
    __shared__ float tile[58][72];
    int m = blockIdx.x;
    int n = blockIdx.y;
    int tx = threadIdx.x, ty = threadIdx.y;
    int tid = ty * 56 + tx;

    // halo zero: rows 0 and 57 (full 72 cols, float4), cols 7 and 64 (rows 1..56)
    if (tid < 36) {
        int r = (tid < 18) ? 0 : 57;
        int c4 = (tid % 18) * 4;
        *(float4*)&tile[r][c4] = make_float4(0.f, 0.f, 0.f, 0.f);
    } else if (tid < 36 + 112) {
        int t = tid - 36;
        int r = 1 + (t >> 1);
        tile[r][(t & 1) ? 64 : 7] = 0.f;
    }

    // interior fill: 56 rows x 7 uint4 (8 halves) each, all 16B aligned
    const __half* src = g_y1h + ((size_t)n * MID + m) * HW;
    if (tid < 392) {
        int r = tid / 7, q = tid - r * 7;
        uint4 v = *(const uint4*)(src + r * 56 + q * 8);
        const __half2* hp = (const __half2*)&v;
        float2 f0 = __half22float2(hp[0]);
        float2 f1 = __half22float2(hp[1]);
        float2 f2 = __half22float2(hp[2]);
        float2 f3 = __half22float2(hp[3]);
        float* d = &tile[r + 1][8 + q * 8];
        *(float4*)d       = make_float4(f0.x, f0.y, f1.x, f1.y);
        *(float4*)(d + 4) = make_float4(f2.x, f2.y, f3.x, f3.y);
    }
    __syncthreads();

    float wv[9];
#pragma unroll
    for (int q = 0; q < 9; q++) wv[q] = __ldg(&w2[m * 9 + q]);
    float sc = __ldg(&s2[m]), sh = __ldg(&b2[m]);

    int cs = (m % 40) * 3 + m / 40;
    __half* dst = g_th + ((size_t)n * 128 + cs) * HWP;

    int r0 = ty * 7;
    int cx = tx + 7;
    float a0 = tile[r0][cx],     a1 = tile[r0][cx + 1],     a2 = tile[r0][cx + 2];
    float e0 = tile[r0 + 1][cx], e1 = tile[r0 + 1][cx + 1], e2 = tile[r0 + 1][cx + 2];
#pragma unroll
    for (int i = 0; i < 7; i++) {
        int row = r0 + i;
        float c0 = tile[row + 2][cx], c1 = tile[row + 2][cx + 1], c2 = tile[row + 2][cx + 2];
        float sum = wv[0] * a0;
        sum = fmaf(wv[1], a1, sum); sum = fmaf(wv[2], a2, sum);
        sum = fmaf(wv[3], e0, sum); sum = fmaf(wv[4], e1, sum);
        sum = fmaf(wv[5], e2, sum); sum = fmaf(wv[6], c0, sum);
        sum = fmaf(wv[7], c1, sum); sum = fmaf(wv[8], c2, sum);
        dst[row * WDIM + tx] = __float2half(fmaf(sc, sum, sh));
        a0 = e0; a1 = e1; a2 = e2;
        e0 = c0; e1 = c1; e2 = c2;
    }
}

// ---------------------------------------------------------------------------
// K3: fused conv3 + relu(bn3) + shortcut + add (unchanged)
// ---------------------------------------------------------------------------
__global__ __launch_bounds__(256)
void k_main_m(const float* __restrict__ sh3, const float* __restrict__ shsc,
              float* __restrict__ out) {
    extern __shared__ __align__(16) char BsRaw[];
    uint32_t sbB = smem_u32(BsRaw);

    int tid = threadIdx.x;
    int wid = tid >> 5, lane = tid & 31;
    int nb = (wid & 1) * 64;
    int nbc = (wid & 1) * 8;
    int wt = (wid >> 1) * 2;

    int mt  = blockIdx.x;
    int p0  = blockIdx.y * 128;
    int img = blockIdx.z;
    int rbase = mt * 128 + wt * 16;

    const int sA = (mt == 3) ? 1 : 0;
    const int nA = (mt == 1 || mt == 2) ? 2 : 1;
    const int nchunk = nA + 4;

    const __half* srcA = g_th + (size_t)img * 128 * HWP;
    const __half* srcB = g_xh + (size_t)img * 256 * HWP;

    float acc[2][8][4];
#pragma unroll
    for (int t = 0; t < 2; t++)
#pragma unroll
        for (int j = 0; j < 8; j++)
#pragma unroll
            for (int q = 0; q < 4; q++) acc[t][j][q] = 0.f;

    float v3[2][2], vsc[2][2];
#pragma unroll
    for (int t = 0; t < 2; t++)
#pragma unroll
        for (int h = 0; h < 2; h++) {
            int co = rbase + t * 16 + (lane >> 2) + h * 8;
            bool ok = co < COUT;
            v3[t][h]  = ok ? sh3[co]  : 0.f;
            vsc[t][h] = ok ? shsc[co] : 0.f;
        }

    int lk = tid >> 4, lc = tid & 15;

    auto issue = [&](int s) {
        const __half* src; int kbase;
        if (s < nA) { src = srcA; kbase = (sA + s) * 64; }
        else        { src = srcB; kbase = (s - nA) * 64; }
        uint32_t db = sbB + (s & (STAGES - 1)) * 16384;
#pragma unroll
        for (int it = 0; it < 4; it++) {
            int k = lk + it * 16;
            const __half* gp = src + (size_t)(kbase + k) * HWP + p0 + lc * 8;
            uint32_t dst = db + k * 256 + ((lc ^ (k & 7)) << 4);
            asm volatile("cp.async.cg.shared.global [%0], [%1], 16;"
                         :: "r"(dst), "l"(gp));
        }
        asm volatile("cp.async.commit_group;");
    };

    issue(0); issue(1); issue(2);

    const int rowl = ((lane >> 3) & 1) * 8 + (lane & 7);
    const int csel = lane >> 4;

    for (int c = 0; c < nchunk; c++) {
        if (c < nchunk - 2)       asm volatile("cp.async.wait_group 2;");
        else if (c == nchunk - 2) asm volatile("cp.async.wait_group 1;");
        else                      asm volatile("cp.async.wait_group 0;");
        __syncthreads();

        uint32_t stageb = sbB + (c & (STAGES - 1)) * 16384;

#pragma unroll
        for (int h = 0; h < 2; h++) {
            int c32 = (c < nA) ? (sA + c) * 2 + h : (c - nA) * 2 + h;
            const __half* fb = (c < nA)
                ? g_fA + ((size_t)((mt * 8  + c32 * 2) * 8 + wt) * 32 + lane) * 8
                : g_fB + ((size_t)((mt * 16 + c32 * 2) * 8 + wt) * 32 + lane) * 8;
            uint4 af[2][2];
#pragma unroll
            for (int g = 0; g < 2; g++)
#pragma unroll
                for (int t = 0; t < 2; t++)
                    af[g][t] = *(const uint4*)(fb + ((size_t)g * 8 + t) * 32 * 8);

            uint32_t base = stageb + h * 8192;
#pragma unroll
            for (int g = 0; g < 2; g++) {
                int row = g * 16 + rowl;
#pragma unroll
                for (int jp = 0; jp < 4; jp++) {
                    int c16 = nbc + jp * 2 + csel;
                    uint32_t addr = base + row * 256 + ((c16 ^ (row & 7)) << 4);
                    uint32_t b0, b1, b2, b3;
                    asm volatile(
                        "ldmatrix.sync.aligned.m8n8.x4.trans.shared.b16 {%0,%1,%2,%3}, [%4];"
                        : "=r"(b0), "=r"(b1), "=r"(b2), "=r"(b3) : "r"(addr));
                    mma16h(acc[0][jp * 2],     af[g][0], b0, b1);
                    mma16h(acc[1][jp * 2],     af[g][1], b0, b1);
                    mma16h(acc[0][jp * 2 + 1], af[g][0], b2, b3);
                    mma16h(acc[1][jp * 2 + 1], af[g][1], b2, b3);
                }
            }
        }

        if (c == nA - 1) {
#pragma unroll
            for (int t = 0; t < 2; t++)
#pragma unroll
                for (int j = 0; j < 8; j++)
#pragma unroll
                    for (int q = 0; q < 4; q++)
                        acc[t][j][q] = fmaxf(acc[t][j][q] + v3[t][q >> 1], 0.f);
        }

        if (c + STAGES - 1 < nchunk) issue(c + STAGES - 1);
    }

#pragma unroll
    for (int t = 0; t < 2; t++) {
#pragma unroll
        for (int h = 0; h < 2; h++) {
            int co = rbase + t * 16 + (lane >> 2) + h * 8;
            if (co >= COUT) continue;
            float* orow = out + ((size_t)img * COUT + co) * HW;
            float bv = vsc[t][h];
#pragma unroll
            for (int j = 0; j < 8; j++) {
                int p = p0 + nb + j * 8 + 2 * (lane & 3);
                if (p < HW) {
                    float2 v;
                    v.x = acc[t][j][h * 2 + 0] + bv;
                    v.y = acc[t][j][h * 2 + 1] + bv;
                    *(float2*)(orow + p) = v;
                }
            }
        }
    }
}

// ---------------------------------------------------------------------------
extern "C" void kernel_launch(void* const* d_in, const int* in_sizes, int n_in,
                              void* d_out, int out_size) {
    const float* x   = (const float*)d_in[0];
    const float* w1  = (const float*)d_in[1];
    const float* s1  = (const float*)d_in[2];
    const float* b1  = (const float*)d_in[3];
    const float* w2  = (const float*)d_in[4];
    const float* s2  = (const float*)d_in[5];
    const float* b2  = (const float*)d_in[6];
    const float* w3  = (const float*)d_in[7];
    const float* s3  = (const float*)d_in[8];
    const float* b3  = (const float*)d_in[9];
    const float* wsc = (const float*)d_in[10];
    const float* ssc = (const float*)d_in[11];
    const float* bsc = (const float*)d_in[12];
    float* out = (float*)d_out;

    static int smem_set = 0;
    if (!smem_set) {
        cudaFuncSetAttribute(k_main_m, cudaFuncAttributeMaxDynamicSharedMemorySize,
                             STAGES * 16384);
        cudaFuncSetAttribute(k_conv1_t, cudaFuncAttributeMaxDynamicSharedMemorySize,
                             STAGES * 16384);
        smem_set = 1;
    }

    int nfold = 4 * 8 * 8 * 32 * 8 + 4 * 16 * 8 * 32 * 8 + 16 * 8 * 32 * 8;
    k_fold<<<(nfold + 255) / 256, 256>>>(w3, s3, wsc, ssc, w1, s1);
    k_cvt<<<(NB * CIN * (HW / 4) + 255) / 256, 256>>>(x);
    k_conv1_t<<<dim3(25, NB), 256, STAGES * 16384>>>(b1);
    k_dw<<<dim3(MID, NB), dim3(56, 8)>>>(w2, s2, b2);
    k_main_m<<<dim3(4, 25, NB), 256, STAGES * 16384>>>(b3, bsc, out);
}